// round 3
// baseline (speedup 1.0000x reference)
#include <cuda_runtime.h>
#include <math.h>

#define TOKENS 2048
#define DM 768
#define DFF 3072
#define NEXP 8
#define SEQ 1024
#define NH 12
#define BH 24
#define HD 64
#define NSLOTS (2 * TOKENS)

// ---------------- scratch (static device globals; no allocations) ----------------
__device__ float g_xn1[TOKENS * DM];
__device__ float g_q[TOKENS * DM];
__device__ float g_k[TOKENS * DM];
__device__ float g_v[TOKENS * DM];
__device__ float g_scores[(size_t)BH * SEQ * SEQ];    // 96 MB
__device__ float g_attn[TOKENS * DM];
__device__ float g_xn2[TOKENS * DM];
__device__ float g_hbuf[(size_t)NSLOTS * DFF];        // 50 MB (compact expert hidden)
__device__ int   g_cnt[NEXP];
__device__ int   g_off[NEXP];
__device__ int   g_fill[NEXP];
__device__ int   g_top_e[NSLOTS];                      // per token: expert1, expert2
__device__ float g_top_g[NSLOTS];                      // per token: gate1, gate2
__device__ int   g_slot_tok[NSLOTS];                   // compact slot -> token
__device__ float g_slot_gate[NSLOTS];                  // compact slot -> gate

// ---------------- utility ----------------
__global__ void zero_cnt_kernel() {
    int t = threadIdx.x;
    if (t < NEXP) { g_cnt[t] = 0; g_fill[t] = 0; }
}

// ---------------- layernorm (one block per token row) ----------------
__global__ void ln_kernel(const float* __restrict__ x, const float* __restrict__ gam,
                          const float* __restrict__ bet, float* __restrict__ y) {
    int row = blockIdx.x;
    int tid = threadIdx.x;  // 256
    __shared__ float sx[DM];
    __shared__ float red[256];
    const float* xr = x + (size_t)row * DM;
    float s = 0.f;
    for (int i = tid; i < DM; i += 256) { float v = xr[i]; sx[i] = v; s += v; }
    red[tid] = s; __syncthreads();
    for (int o = 128; o > 0; o >>= 1) { if (tid < o) red[tid] += red[tid + o]; __syncthreads(); }
    float m = red[0] * (1.0f / DM);
    __syncthreads();
    float s2 = 0.f;
    for (int i = tid; i < DM; i += 256) { float d = sx[i] - m; s2 += d * d; }
    red[tid] = s2; __syncthreads();
    for (int o = 128; o > 0; o >>= 1) { if (tid < o) red[tid] += red[tid + o]; __syncthreads(); }
    float var = red[0] * (1.0f / DM);
    float r = rsqrtf(var + 1e-5f);
    for (int i = tid; i < DM; i += 256)
        y[(size_t)row * DM + i] = (sx[i] - m) * r * gam[i] + bet[i];
}

// ---------------- generic dense SGEMM: C[M,N] = A[M,K]@B[K,N] (+bias)(+res) ----------------
// 64x64 tile, BK=16, 256 threads, 4x4 per thread. M,N multiples of 64; K multiple of 16.
__global__ void sgemm64(const float* __restrict__ A, const float* __restrict__ B,
                        const float* __restrict__ bias, const float* __restrict__ res,
                        float* __restrict__ C, int N, int Kdim) {
    __shared__ float As[16][68];  // [k][m]
    __shared__ float Bs[16][68];  // [k][n]
    int tid = threadIdx.x;
    int row0 = blockIdx.y * 64, col0 = blockIdx.x * 64;
    int ar = tid >> 2, ak = (tid & 3) * 4;
    int br_ = tid >> 4, bc = (tid & 15) * 4;
    int tx = tid & 15, ty = tid >> 4;
    const float* Ap = A + (size_t)(row0 + ar) * Kdim + ak;
    const float* Bp = B + (size_t)br_ * N + col0 + bc;
    float acc[4][4] = {};
    for (int k0 = 0; k0 < Kdim; k0 += 16) {
        float4 av = *(const float4*)(Ap + k0);
        As[ak + 0][ar] = av.x; As[ak + 1][ar] = av.y; As[ak + 2][ar] = av.z; As[ak + 3][ar] = av.w;
        float4 bv = *(const float4*)(Bp + (size_t)k0 * N);
        *(float4*)&Bs[br_][bc] = bv;
        __syncthreads();
#pragma unroll
        for (int kk = 0; kk < 16; kk++) {
            float4 a4 = *(float4*)&As[kk][ty * 4];
            float4 b4 = *(float4*)&Bs[kk][tx * 4];
            float ra[4] = {a4.x, a4.y, a4.z, a4.w};
            float rb[4] = {b4.x, b4.y, b4.z, b4.w};
#pragma unroll
            for (int i = 0; i < 4; i++)
#pragma unroll
                for (int j = 0; j < 4; j++) acc[i][j] += ra[i] * rb[j];
        }
        __syncthreads();
    }
#pragma unroll
    for (int i = 0; i < 4; i++) {
        int r = row0 + ty * 4 + i;
#pragma unroll
        for (int j = 0; j < 4; j++) {
            int c = col0 + tx * 4 + j;
            float v = acc[i][j];
            if (bias) v += bias[c];
            if (res)  v += res[(size_t)r * N + c];
            C[(size_t)r * N + c] = v;
        }
    }
}

// ---------------- attention scores: S = Q Kt * 0.125 (causal tiles only) ----------------
__global__ void attn_scores_kernel(const float* __restrict__ Q, const float* __restrict__ Km) {
    int bh = blockIdx.z; int b = bh / NH, h = bh % NH;
    int qt = blockIdx.y, kt = blockIdx.x;
    if (kt > qt) return;
    int q0 = qt * 64, k0 = kt * 64;
    __shared__ float Qs[64][68];  // [d][m]
    __shared__ float Ks[64][68];  // [d][n]
    int tid = threadIdx.x;
    int lr = tid & 15, rr = tid >> 4;
    size_t base_q = (size_t)(b * SEQ + q0) * DM + h * HD;
    size_t base_k = (size_t)(b * SEQ + k0) * DM + h * HD;
#pragma unroll
    for (int c = 0; c < 4; c++) {
        int r = rr + 16 * c;
        float4 qv = *(const float4*)&Q[base_q + (size_t)r * DM + lr * 4];
        Qs[lr * 4 + 0][r] = qv.x; Qs[lr * 4 + 1][r] = qv.y; Qs[lr * 4 + 2][r] = qv.z; Qs[lr * 4 + 3][r] = qv.w;
        float4 kv = *(const float4*)&Km[base_k + (size_t)r * DM + lr * 4];
        Ks[lr * 4 + 0][r] = kv.x; Ks[lr * 4 + 1][r] = kv.y; Ks[lr * 4 + 2][r] = kv.z; Ks[lr * 4 + 3][r] = kv.w;
    }
    __syncthreads();
    int tx = tid & 15, ty = tid >> 4;
    float acc[4][4] = {};
#pragma unroll 8
    for (int d = 0; d < 64; d++) {
        float4 a4 = *(float4*)&Qs[d][ty * 4];
        float4 b4 = *(float4*)&Ks[d][tx * 4];
        float ra[4] = {a4.x, a4.y, a4.z, a4.w};
        float rb[4] = {b4.x, b4.y, b4.z, b4.w};
#pragma unroll
        for (int i = 0; i < 4; i++)
#pragma unroll
            for (int j = 0; j < 4; j++) acc[i][j] += ra[i] * rb[j];
    }
    float* out = g_scores + (size_t)bh * SEQ * SEQ;
#pragma unroll
    for (int i = 0; i < 4; i++)
#pragma unroll
        for (int j = 0; j < 4; j++)
            out[(size_t)(q0 + ty * 4 + i) * SEQ + k0 + tx * 4 + j] = acc[i][j] * 0.125f;
}

// ---------------- causal row softmax (in-place on g_scores; zeros beyond q) ----------------
__global__ void softmax_kernel() {
    int q = blockIdx.x, bh = blockIdx.y;
    float* row = g_scores + (size_t)bh * SEQ * SEQ + (size_t)q * SEQ;
    int n = q + 1, tid = threadIdx.x;
    __shared__ float red[256];
    float m = -1e30f;
    for (int i = tid; i < n; i += 256) m = fmaxf(m, row[i]);
    red[tid] = m; __syncthreads();
    for (int o = 128; o > 0; o >>= 1) { if (tid < o) red[tid] = fmaxf(red[tid], red[tid + o]); __syncthreads(); }
    m = red[0]; __syncthreads();
    float s = 0.f;
    for (int i = tid; i < n; i += 256) s += expf(row[i] - m);
    red[tid] = s; __syncthreads();
    for (int o = 128; o > 0; o >>= 1) { if (tid < o) red[tid] += red[tid + o]; __syncthreads(); }
    float inv = 1.0f / red[0];
    for (int i = tid; i < n; i += 256) row[i] = expf(row[i] - m) * inv;
    for (int i = n + tid; i < SEQ; i += 256) row[i] = 0.0f;
}

// ---------------- attention output: O = P @ V, written as [b,s,h,d] ----------------
__global__ void attn_av_kernel(const float* __restrict__ V) {
    int bh = blockIdx.z; int b = bh / NH, h = bh % NH;
    int q0 = blockIdx.y * 64;
    __shared__ float Ps[16][68];  // [k][q]
    __shared__ float Vs[16][68];  // [k][d]
    int tid = threadIdx.x;
    int ar = tid >> 2, ak = (tid & 3) * 4;
    int br_ = tid >> 4, bc = (tid & 15) * 4;
    int tx = tid & 15, ty = tid >> 4;
    const float* Prow = g_scores + (size_t)bh * SEQ * SEQ + (size_t)(q0 + ar) * SEQ + ak;
    size_t vbase = (size_t)(b * SEQ + br_) * DM + h * HD + bc;
    float acc[4][4] = {};
    int kmax = q0 + 64;  // causal: no probability mass beyond the q-tile diagonal
    for (int k0 = 0; k0 < kmax; k0 += 16) {
        float4 pv = *(const float4*)(Prow + k0);
        Ps[ak + 0][ar] = pv.x; Ps[ak + 1][ar] = pv.y; Ps[ak + 2][ar] = pv.z; Ps[ak + 3][ar] = pv.w;
        float4 vv = *(const float4*)&V[vbase + (size_t)k0 * DM];
        *(float4*)&Vs[br_][bc] = vv;
        __syncthreads();
#pragma unroll
        for (int kk = 0; kk < 16; kk++) {
            float4 a4 = *(float4*)&Ps[kk][ty * 4];
            float4 b4 = *(float4*)&Vs[kk][tx * 4];
            float ra[4] = {a4.x, a4.y, a4.z, a4.w};
            float rb[4] = {b4.x, b4.y, b4.z, b4.w};
#pragma unroll
            for (int i = 0; i < 4; i++)
#pragma unroll
                for (int j = 0; j < 4; j++) acc[i][j] += ra[i] * rb[j];
        }
        __syncthreads();
    }
#pragma unroll
    for (int i = 0; i < 4; i++)
#pragma unroll
        for (int j = 0; j < 4; j++)
            g_attn[(size_t)(b * SEQ + q0 + ty * 4 + i) * DM + h * HD + tx * 4 + j] = acc[i][j];
}

// ---------------- router phase 1: logits, top-2, gates, per-expert counts ----------------
__global__ void router_kernel(const float* __restrict__ Wr, const float* __restrict__ br) {
    int t = blockIdx.x, tid = threadIdx.x;  // 64 threads
    float acc[NEXP] = {};
    const float* xr = g_xn2 + (size_t)t * DM;
    for (int d = tid; d < DM; d += 64) {
        float xv = xr[d];
        const float* w = Wr + (size_t)d * NEXP;
#pragma unroll
        for (int e = 0; e < NEXP; e++) acc[e] += xv * w[e];
    }
    __shared__ float sh[64][NEXP + 1];
#pragma unroll
    for (int e = 0; e < NEXP; e++) sh[tid][e] = acc[e];
    __syncthreads();
    if (tid < NEXP) {
        float s = br[tid];
        for (int i = 0; i < 64; i++) s += sh[i][tid];
        sh[0][tid] = s;
    }
    __syncthreads();
    if (tid == 0) {
        float l[NEXP];
#pragma unroll
        for (int e = 0; e < NEXP; e++) l[e] = sh[0][e];
        int i1 = 0;
        for (int e = 1; e < NEXP; e++) if (l[e] > l[i1]) i1 = e;
        int i2 = (i1 == 0) ? 1 : 0;
        for (int e = 0; e < NEXP; e++) if (e != i1 && l[e] > l[i2]) i2 = e;
        float g1 = 1.0f / (1.0f + expf(l[i2] - l[i1]));
        float g2 = 1.0f - g1;
        g_top_e[2 * t] = i1; g_top_g[2 * t] = g1;
        g_top_e[2 * t + 1] = i2; g_top_g[2 * t + 1] = g2;
        atomicAdd(&g_cnt[i1], 1);
        atomicAdd(&g_cnt[i2], 1);
    }
}

// ---------------- router phase 2: exclusive prefix over expert counts ----------------
__global__ void offsets_kernel() {
    if (threadIdx.x == 0) {
        int acc = 0;
#pragma unroll
        for (int e = 0; e < NEXP; e++) { g_off[e] = acc; acc += g_cnt[e]; }
    }
}

// ---------------- router phase 3: scatter tokens into compact slots ----------------
__global__ void scatter_kernel() {
    int i = blockIdx.x * 256 + threadIdx.x;
    if (i >= NSLOTS) return;
    int e = g_top_e[i];
    int p = atomicAdd(&g_fill[e], 1);
    int slot = g_off[e] + p;
    g_slot_tok[slot] = i >> 1;
    g_slot_gate[slot] = g_top_g[i];
}

__device__ __forceinline__ float gelu_exact(float x) {
    return 0.5f * x * (1.0f + erff(x * 0.70710678118654752f));
}

// ---------------- expert GEMM1: hbuf = gelu(gather(xn2) @ W1[e] + b1[e]) ----------------
__global__ void moe_gemm1(const float* __restrict__ W1, const float* __restrict__ b1) {
    int e = blockIdx.z;
    int cnt = g_cnt[e];
    int off = g_off[e];
    int m0 = blockIdx.y * 64;
    if (m0 >= cnt) return;
    int col0 = blockIdx.x * 64;
    __shared__ float As[16][68];
    __shared__ float Bs[16][68];
    int tid = threadIdx.x;
    int ar = tid >> 2, ak = (tid & 3) * 4;
    int br_ = tid >> 4, bc = (tid & 15) * 4;
    int tx = tid & 15, ty = tid >> 4;
    int arow = m0 + ar;
    bool aval = arow < cnt;
    const float* Ap = nullptr;
    if (aval) {
        int tok = g_slot_tok[off + arow];
        Ap = g_xn2 + (size_t)tok * DM + ak;
    }
    const float* Bp = W1 + (size_t)e * DM * DFF + (size_t)br_ * DFF + col0 + bc;
    float acc[4][4] = {};
    for (int k0 = 0; k0 < DM; k0 += 16) {
        float4 av = aval ? *(const float4*)(Ap + k0) : make_float4(0.f, 0.f, 0.f, 0.f);
        As[ak + 0][ar] = av.x; As[ak + 1][ar] = av.y; As[ak + 2][ar] = av.z; As[ak + 3][ar] = av.w;
        float4 bv = *(const float4*)(Bp + (size_t)k0 * DFF);
        *(float4*)&Bs[br_][bc] = bv;
        __syncthreads();
#pragma unroll
        for (int kk = 0; kk < 16; kk++) {
            float4 a4 = *(float4*)&As[kk][ty * 4];
            float4 b4 = *(float4*)&Bs[kk][tx * 4];
            float ra[4] = {a4.x, a4.y, a4.z, a4.w};
            float rb[4] = {b4.x, b4.y, b4.z, b4.w};
#pragma unroll
            for (int i = 0; i < 4; i++)
#pragma unroll
                for (int j = 0; j < 4; j++) acc[i][j] += ra[i] * rb[j];
        }
        __syncthreads();
    }
#pragma unroll
    for (int i = 0; i < 4; i++) {
        int r = m0 + ty * 4 + i;
        if (r < cnt) {
#pragma unroll
            for (int j = 0; j < 4; j++) {
                int c = col0 + tx * 4 + j;
                float v = gelu_exact(acc[i][j] + b1[(size_t)e * DFF + c]);
                g_hbuf[(size_t)(off + r) * DFF + c] = v;
            }
        }
    }
}

// ---------------- expert GEMM2: out[tok] += gate * (hbuf @ W2[e] + b2[e]) ----------------
__global__ void moe_gemm2(const float* __restrict__ W2, const float* __restrict__ b2,
                          float* __restrict__ out) {
    int e = blockIdx.z;
    int cnt = g_cnt[e];
    int off = g_off[e];
    int m0 = blockIdx.y * 64;
    if (m0 >= cnt) return;
    int col0 = blockIdx.x * 64;
    __shared__ float As[16][68];
    __shared__ float Bs[16][68];
    int tid = threadIdx.x;
    int ar = tid >> 2, ak = (tid & 3) * 4;
    int br_ = tid >> 4, bc = (tid & 15) * 4;
    int tx = tid & 15, ty = tid >> 4;
    int arow = m0 + ar;
    bool aval = arow < cnt;
    const float* Ap = g_hbuf + (size_t)(off + arow) * DFF + ak;
    const float* Bp = W2 + (size_t)e * DFF * DM + (size_t)br_ * DM + col0 + bc;
    float acc[4][4] = {};
    for (int k0 = 0; k0 < DFF; k0 += 16) {
        float4 av = aval ? *(const float4*)(Ap + k0) : make_float4(0.f, 0.f, 0.f, 0.f);
        As[ak + 0][ar] = av.x; As[ak + 1][ar] = av.y; As[ak + 2][ar] = av.z; As[ak + 3][ar] = av.w;
        float4 bv = *(const float4*)(Bp + (size_t)k0 * DM);
        *(float4*)&Bs[br_][bc] = bv;
        __syncthreads();
#pragma unroll
        for (int kk = 0; kk < 16; kk++) {
            float4 a4 = *(float4*)&As[kk][ty * 4];
            float4 b4 = *(float4*)&Bs[kk][tx * 4];
            float ra[4] = {a4.x, a4.y, a4.z, a4.w};
            float rb[4] = {b4.x, b4.y, b4.z, b4.w};
#pragma unroll
            for (int i = 0; i < 4; i++)
#pragma unroll
                for (int j = 0; j < 4; j++) acc[i][j] += ra[i] * rb[j];
        }
        __syncthreads();
    }
#pragma unroll
    for (int i = 0; i < 4; i++) {
        int r = m0 + ty * 4 + i;
        if (r < cnt) {
            int slot = off + r;
            int tok = g_slot_tok[slot];
            float gt = g_slot_gate[slot];
#pragma unroll
            for (int j = 0; j < 4; j++) {
                int c = col0 + tx * 4 + j;
                float v = (acc[i][j] + b2[(size_t)e * DM + c]) * gt;
                atomicAdd(&out[(size_t)tok * DM + c], v);
            }
        }
    }
}

// ---------------- launch ----------------
extern "C" void kernel_launch(void* const* d_in, const int* in_sizes, int n_in,
                              void* d_out, int out_size) {
    const float* x     = (const float*)d_in[0];
    const float* ln1_g = (const float*)d_in[1];
    const float* ln1_b = (const float*)d_in[2];
    const float* Wq    = (const float*)d_in[3];
    const float* Wk    = (const float*)d_in[4];
    const float* Wv    = (const float*)d_in[5];
    const float* Wo    = (const float*)d_in[6];
    const float* bo    = (const float*)d_in[7];
    const float* ln2_g = (const float*)d_in[8];
    const float* ln2_b = (const float*)d_in[9];
    const float* Wr    = (const float*)d_in[10];
    const float* br    = (const float*)d_in[11];
    const float* W1    = (const float*)d_in[12];
    const float* b1    = (const float*)d_in[13];
    const float* W2    = (const float*)d_in[14];
    const float* b2    = (const float*)d_in[15];
    float* out = (float*)d_out;

    // device scratch pointers via unified addressing of __device__ globals
    // (kernels reference the globals directly; only cross-kernel I/O uses params)
    float *xn1_p, *q_p, *k_p, *v_p, *attn_p, *xn2_p;
    cudaGetSymbolAddress((void**)&xn1_p, g_xn1);
    cudaGetSymbolAddress((void**)&q_p, g_q);
    cudaGetSymbolAddress((void**)&k_p, g_k);
    cudaGetSymbolAddress((void**)&v_p, g_v);
    cudaGetSymbolAddress((void**)&attn_p, g_attn);
    cudaGetSymbolAddress((void**)&xn2_p, g_xn2);

    zero_cnt_kernel<<<1, 32>>>();
    ln_kernel<<<TOKENS, 256>>>(x, ln1_g, ln1_b, xn1_p);

    dim3 gproj(DM / 64, TOKENS / 64);  // (12, 32)
    sgemm64<<<gproj, 256>>>(xn1_p, Wq, nullptr, nullptr, q_p, DM, DM);
    sgemm64<<<gproj, 256>>>(xn1_p, Wk, nullptr, nullptr, k_p, DM, DM);
    sgemm64<<<gproj, 256>>>(xn1_p, Wv, nullptr, nullptr, v_p, DM, DM);

    attn_scores_kernel<<<dim3(SEQ / 64, SEQ / 64, BH), 256>>>(q_p, k_p);
    softmax_kernel<<<dim3(SEQ, BH), 256>>>();
    attn_av_kernel<<<dim3(1, SEQ / 64, BH), 256>>>(v_p);

    // h = x + attn @ Wo + bo, written DIRECTLY into d_out
    sgemm64<<<gproj, 256>>>(attn_p, Wo, bo, x, out, DM, DM);

    ln_kernel<<<TOKENS, 256>>>(out, ln2_g, ln2_b, xn2_p);

    router_kernel<<<TOKENS, 64>>>(Wr, br);
    offsets_kernel<<<1, 32>>>();
    scatter_kernel<<<(NSLOTS + 255) / 256, 256>>>();

    moe_gemm1<<<dim3(DFF / 64, TOKENS / 64, NEXP), 256>>>(W1, b1);
    moe_gemm2<<<dim3(DM / 64, TOKENS / 64, NEXP), 256>>>(W2, b2, out);
}

// round 6
// speedup vs baseline: 2.3455x; 2.3455x over previous
#include <cuda_runtime.h>
#include <cuda_bf16.h>
#include <stdint.h>
#include <stddef.h>
#include <math.h>

#define TOKENS 2048
#define DM 768
#define DFF 3072
#define NEXP 8
#define SEQ 1024
#define NH 12
#define BH 24
#define HD 64
#define NSLOTS (2 * TOKENS)

// ---------------- scratch (static device globals; no allocations) ----------------
__device__ float g_xn1[TOKENS * DM];
__device__ float g_q[TOKENS * DM];
__device__ float g_k[TOKENS * DM];
__device__ float g_v[TOKENS * DM];
__device__ float g_scores[(size_t)BH * SEQ * SEQ];        // 96 MB
__device__ float g_attn[TOKENS * DM];
__device__ float g_xn2[TOKENS * DM];
__device__ unsigned short g_hbuf[(size_t)NSLOTS * DFF];   // 25 MB expert hidden (bf16 bits)
__device__ int   g_cnt[NEXP];
__device__ int   g_off[NEXP];
__device__ int   g_fill[NEXP];
__device__ int   g_top_e[NSLOTS];
__device__ float g_top_g[NSLOTS];
__device__ int   g_slot_tok[NSLOTS];
__device__ float g_slot_gate[NSLOTS];

// ---------------- small helpers ----------------
__global__ void zero_cnt_kernel() {
    int t = threadIdx.x;
    if (t < NEXP) { g_cnt[t] = 0; g_fill[t] = 0; }
}

__device__ __forceinline__ uint32_t smem_u32(const void* p) {
    return (uint32_t)__cvta_generic_to_shared(p);
}
__device__ __forceinline__ uint32_t packbf(float x, float y) {
    __nv_bfloat162 h = __floats2bfloat162_rn(x, y);
    return *(uint32_t*)&h;
}
__device__ __forceinline__ void ldsm_x4(uint32_t& r0, uint32_t& r1, uint32_t& r2, uint32_t& r3, uint32_t addr) {
    asm volatile("ldmatrix.sync.aligned.m8n8.x4.shared.b16 {%0,%1,%2,%3}, [%4];"
                 : "=r"(r0), "=r"(r1), "=r"(r2), "=r"(r3) : "r"(addr));
}
__device__ __forceinline__ void ldsm_x4_t(uint32_t& r0, uint32_t& r1, uint32_t& r2, uint32_t& r3, uint32_t addr) {
    asm volatile("ldmatrix.sync.aligned.m8n8.x4.trans.shared.b16 {%0,%1,%2,%3}, [%4];"
                 : "=r"(r0), "=r"(r1), "=r"(r2), "=r"(r3) : "r"(addr));
}
__device__ __forceinline__ void mma_bf16(float* c, uint32_t a0, uint32_t a1, uint32_t a2, uint32_t a3,
                                         uint32_t b0, uint32_t b1) {
    asm volatile("mma.sync.aligned.m16n8k16.row.col.f32.bf16.bf16.f32 "
                 "{%0,%1,%2,%3},{%4,%5,%6,%7},{%8,%9},{%0,%1,%2,%3};"
                 : "+f"(c[0]), "+f"(c[1]), "+f"(c[2]), "+f"(c[3])
                 : "r"(a0), "r"(a1), "r"(a2), "r"(a3), "r"(b0), "r"(b1));
}
__device__ __forceinline__ float gelu_exact(float x) {
    return 0.5f * x * (1.0f + erff(x * 0.70710678118654752f));
}

// ---------------- bf16 tensor-core GEMM ----------------
// MODE 0: C = A @ B                       (dense, fp32 A)
// MODE 1: C = A @ B + bias + res         (o-proj)
// MODE 2: hbuf = gelu(gather(xn2) @ W1[e] + b1[e])   (per-expert, bf16 store)
// MODE 3: out[tok] += gate * (hbuf @ W2[e] + b2[e])  (per-expert, atomic)
// CTA: 128x128 tile, BK=32, 256 threads (8 warps, 2x4 -> 64x32 warp tiles)
template<int MODE>
__global__ __launch_bounds__(256, 2)
void bgemm(const float* __restrict__ A, const float* __restrict__ Bw,
           const float* __restrict__ bias, const float* __restrict__ res,
           float* __restrict__ C, int N, int Kdim) {
    int e = (MODE >= 2) ? blockIdx.z : 0;
    int cnt = 0, off = 0;
    if (MODE >= 2) {
        cnt = g_cnt[e];
        off = g_off[e];
        if ((int)blockIdx.y * 128 >= cnt) return;
    }
    const float* Bp = Bw;
    if (MODE == 2) Bp += (size_t)e * DM * DFF;
    if (MODE == 3) Bp += (size_t)e * DFF * DM;

    int m00 = blockIdx.y * 128, col0 = blockIdx.x * 128;

    __shared__ unsigned short As[128][40];   // bf16 bits, padded pitch
    __shared__ unsigned short Bs[32][136];

    int tid = threadIdx.x, lane = tid & 31, warp = tid >> 5;
    int wm = (warp & 1) * 64, wn = (warp >> 1) * 32;

    // A loader: thread -> (row = tid>>1, kchunk = (tid&1)*16)
    int ar = tid >> 1, akc = (tid & 1) * 16;
    // B loader: thread -> (krow = tid>>3, col = (tid&7)*16)
    int bkr = tid >> 3, bc = (tid & 7) * 16;

    bool aval = true;
    const float* arow = nullptr;
    const unsigned short* arow16 = nullptr;
    if (MODE <= 1) {
        arow = A + (size_t)(m00 + ar) * Kdim;
    } else if (MODE == 2) {
        int rc = m00 + ar;
        aval = rc < cnt;
        if (aval) arow = g_xn2 + (size_t)g_slot_tok[off + rc] * DM;
    } else {
        int rc = m00 + ar;
        aval = rc < cnt;
        if (aval) arow16 = g_hbuf + (size_t)(off + rc) * DFF;
    }

    float acc[4][4][4] = {};

    for (int k0 = 0; k0 < Kdim; k0 += 32) {
        // ---- load A tile (convert fp32 -> bf16 unless MODE 3) ----
        uint4 ua0, ua1;
        if (MODE == 3) {
            if (aval) {
                ua0 = *(const uint4*)(arow16 + k0 + akc);
                ua1 = *(const uint4*)(arow16 + k0 + akc + 8);
            } else { ua0 = make_uint4(0u, 0u, 0u, 0u); ua1 = ua0; }
        } else {
            if (aval) {
                const float* s = arow + k0 + akc;
                float4 v0 = *(const float4*)(s + 0);
                float4 v1 = *(const float4*)(s + 4);
                float4 v2 = *(const float4*)(s + 8);
                float4 v3 = *(const float4*)(s + 12);
                ua0 = make_uint4(packbf(v0.x, v0.y), packbf(v0.z, v0.w),
                                 packbf(v1.x, v1.y), packbf(v1.z, v1.w));
                ua1 = make_uint4(packbf(v2.x, v2.y), packbf(v2.z, v2.w),
                                 packbf(v3.x, v3.y), packbf(v3.z, v3.w));
            } else { ua0 = make_uint4(0u, 0u, 0u, 0u); ua1 = ua0; }
        }
        *(uint4*)&As[ar][akc] = ua0;
        *(uint4*)&As[ar][akc + 8] = ua1;

        // ---- load B tile (fp32 -> bf16) ----
        {
            const float* s = Bp + (size_t)(k0 + bkr) * N + col0 + bc;
            float4 w0 = *(const float4*)(s + 0);
            float4 w1 = *(const float4*)(s + 4);
            float4 w2 = *(const float4*)(s + 8);
            float4 w3 = *(const float4*)(s + 12);
            *(uint4*)&Bs[bkr][bc] = make_uint4(packbf(w0.x, w0.y), packbf(w0.z, w0.w),
                                               packbf(w1.x, w1.y), packbf(w1.z, w1.w));
            *(uint4*)&Bs[bkr][bc + 8] = make_uint4(packbf(w2.x, w2.y), packbf(w2.z, w2.w),
                                                   packbf(w3.x, w3.y), packbf(w3.z, w3.w));
        }
        __syncthreads();

#pragma unroll
        for (int ks = 0; ks < 2; ks++) {
            int kk = ks * 16;
            uint32_t a[4][4];
#pragma unroll
            for (int mi = 0; mi < 4; mi++) {
                uint32_t addr = smem_u32(&As[wm + mi * 16 + (lane & 15)][kk + (lane >> 4) * 8]);
                ldsm_x4(a[mi][0], a[mi][1], a[mi][2], a[mi][3], addr);
            }
            uint32_t b[4][2];
#pragma unroll
            for (int nb = 0; nb < 2; nb++) {
                uint32_t addr = smem_u32(&Bs[kk + (lane & 15)][wn + nb * 16 + (lane >> 4) * 8]);
                ldsm_x4_t(b[nb * 2][0], b[nb * 2][1], b[nb * 2 + 1][0], b[nb * 2 + 1][1], addr);
            }
#pragma unroll
            for (int mi = 0; mi < 4; mi++)
#pragma unroll
                for (int nj = 0; nj < 4; nj++)
                    mma_bf16(acc[mi][nj], a[mi][0], a[mi][1], a[mi][2], a[mi][3],
                             b[nj][0], b[nj][1]);
        }
        __syncthreads();
    }

    // ---- epilogue ----
    int g = lane >> 2, t4 = lane & 3;
#pragma unroll
    for (int mi = 0; mi < 4; mi++) {
#pragma unroll
        for (int h2 = 0; h2 < 2; h2++) {
            int rloc = wm + mi * 16 + g + h2 * 8;
            if (MODE >= 2) {
                int rc = m00 + rloc;
                if (rc >= cnt) continue;
                int slot = off + rc;
                if (MODE == 2) {
                    size_t base = (size_t)slot * DFF;
#pragma unroll
                    for (int nj = 0; nj < 4; nj++) {
                        int col = col0 + wn + nj * 8 + 2 * t4;
                        float v0 = gelu_exact(acc[mi][nj][h2 * 2 + 0] + bias[(size_t)e * DFF + col]);
                        float v1 = gelu_exact(acc[mi][nj][h2 * 2 + 1] + bias[(size_t)e * DFF + col + 1]);
                        uint32_t p = packbf(v0, v1);
                        *(uint32_t*)&g_hbuf[base + col] = p;
                    }
                } else {
                    int tok = g_slot_tok[slot];
                    float gt = g_slot_gate[slot];
#pragma unroll
                    for (int nj = 0; nj < 4; nj++) {
                        int col = col0 + wn + nj * 8 + 2 * t4;
                        float v0 = (acc[mi][nj][h2 * 2 + 0] + bias[(size_t)e * DM + col]) * gt;
                        float v1 = (acc[mi][nj][h2 * 2 + 1] + bias[(size_t)e * DM + col + 1]) * gt;
                        atomicAdd(&C[(size_t)tok * DM + col], v0);
                        atomicAdd(&C[(size_t)tok * DM + col + 1], v1);
                    }
                }
            } else {
                int row = m00 + rloc;
#pragma unroll
                for (int nj = 0; nj < 4; nj++) {
                    int col = col0 + wn + nj * 8 + 2 * t4;
                    float v0 = acc[mi][nj][h2 * 2 + 0];
                    float v1 = acc[mi][nj][h2 * 2 + 1];
                    if (MODE == 1) {
                        v0 += bias[col] + res[(size_t)row * N + col];
                        v1 += bias[col + 1] + res[(size_t)row * N + col + 1];
                    }
                    *(float2*)&C[(size_t)row * N + col] = make_float2(v0, v1);
                }
            }
        }
    }
}

// ---------------- layernorm (one block per token row) ----------------
__global__ void ln_kernel(const float* __restrict__ x, const float* __restrict__ gam,
                          const float* __restrict__ bet, float* __restrict__ y) {
    int row = blockIdx.x;
    int tid = threadIdx.x;  // 256
    __shared__ float sx[DM];
    __shared__ float red[256];
    const float* xr = x + (size_t)row * DM;
    float s = 0.f;
    for (int i = tid; i < DM; i += 256) { float v = xr[i]; sx[i] = v; s += v; }
    red[tid] = s; __syncthreads();
    for (int o = 128; o > 0; o >>= 1) { if (tid < o) red[tid] += red[tid + o]; __syncthreads(); }
    float m = red[0] * (1.0f / DM);
    __syncthreads();
    float s2 = 0.f;
    for (int i = tid; i < DM; i += 256) { float d = sx[i] - m; s2 += d * d; }
    red[tid] = s2; __syncthreads();
    for (int o = 128; o > 0; o >>= 1) { if (tid < o) red[tid] += red[tid + o]; __syncthreads(); }
    float var = red[0] * (1.0f / DM);
    float r = rsqrtf(var + 1e-5f);
    for (int i = tid; i < DM; i += 256)
        y[(size_t)row * DM + i] = (sx[i] - m) * r * gam[i] + bet[i];
}

// ---------------- attention scores: S = Q Kt * 0.125 (causal tiles only) ----------------
__global__ void attn_scores_kernel(const float* __restrict__ Q, const float* __restrict__ Km) {
    int bh = blockIdx.z; int b = bh / NH, h = bh % NH;
    int qt = blockIdx.y, kt = blockIdx.x;
    if (kt > qt) return;
    int q0 = qt * 64, k0 = kt * 64;
    __shared__ float Qs[64][68];
    __shared__ float Ks[64][68];
    int tid = threadIdx.x;
    int lr = tid & 15, rr = tid >> 4;
    size_t base_q = (size_t)(b * SEQ + q0) * DM + h * HD;
    size_t base_k = (size_t)(b * SEQ + k0) * DM + h * HD;
#pragma unroll
    for (int c = 0; c < 4; c++) {
        int r = rr + 16 * c;
        float4 qv = *(const float4*)&Q[base_q + (size_t)r * DM + lr * 4];
        Qs[lr * 4 + 0][r] = qv.x; Qs[lr * 4 + 1][r] = qv.y; Qs[lr * 4 + 2][r] = qv.z; Qs[lr * 4 + 3][r] = qv.w;
        float4 kv = *(const float4*)&Km[base_k + (size_t)r * DM + lr * 4];
        Ks[lr * 4 + 0][r] = kv.x; Ks[lr * 4 + 1][r] = kv.y; Ks[lr * 4 + 2][r] = kv.z; Ks[lr * 4 + 3][r] = kv.w;
    }
    __syncthreads();
    int tx = tid & 15, ty = tid >> 4;
    float acc[4][4] = {};
#pragma unroll 8
    for (int d = 0; d < 64; d++) {
        float4 a4 = *(float4*)&Qs[d][ty * 4];
        float4 b4 = *(float4*)&Ks[d][tx * 4];
        float ra[4] = {a4.x, a4.y, a4.z, a4.w};
        float rb[4] = {b4.x, b4.y, b4.z, b4.w};
#pragma unroll
        for (int i = 0; i < 4; i++)
#pragma unroll
            for (int j = 0; j < 4; j++) acc[i][j] += ra[i] * rb[j];
    }
    float* out = g_scores + (size_t)bh * SEQ * SEQ;
#pragma unroll
    for (int i = 0; i < 4; i++)
#pragma unroll
        for (int j = 0; j < 4; j++)
            out[(size_t)(q0 + ty * 4 + i) * SEQ + k0 + tx * 4 + j] = acc[i][j] * 0.125f;
}

// ---------------- causal row softmax ----------------
__global__ void softmax_kernel() {
    int q = blockIdx.x, bh = blockIdx.y;
    float* row = g_scores + (size_t)bh * SEQ * SEQ + (size_t)q * SEQ;
    int n = q + 1, tid = threadIdx.x;
    __shared__ float red[256];
    float m = -1e30f;
    for (int i = tid; i < n; i += 256) m = fmaxf(m, row[i]);
    red[tid] = m; __syncthreads();
    for (int o = 128; o > 0; o >>= 1) { if (tid < o) red[tid] = fmaxf(red[tid], red[tid + o]); __syncthreads(); }
    m = red[0]; __syncthreads();
    float s = 0.f;
    for (int i = tid; i < n; i += 256) s += expf(row[i] - m);
    red[tid] = s; __syncthreads();
    for (int o = 128; o > 0; o >>= 1) { if (tid < o) red[tid] += red[tid + o]; __syncthreads(); }
    float inv = 1.0f / red[0];
    for (int i = tid; i < n; i += 256) row[i] = expf(row[i] - m) * inv;
    for (int i = n + tid; i < SEQ; i += 256) row[i] = 0.0f;
}

// ---------------- attention output: O = P @ V ----------------
__global__ void attn_av_kernel(const float* __restrict__ V) {
    int bh = blockIdx.z; int b = bh / NH, h = bh % NH;
    int q0 = blockIdx.y * 64;
    __shared__ float Ps[16][68];
    __shared__ float Vs[16][68];
    int tid = threadIdx.x;
    int ar = tid >> 2, ak = (tid & 3) * 4;
    int br_ = tid >> 4, bc = (tid & 15) * 4;
    int tx = tid & 15, ty = tid >> 4;
    const float* Prow = g_scores + (size_t)bh * SEQ * SEQ + (size_t)(q0 + ar) * SEQ + ak;
    size_t vbase = (size_t)(b * SEQ + br_) * DM + h * HD + bc;
    float acc[4][4] = {};
    int kmax = q0 + 64;
    for (int k0 = 0; k0 < kmax; k0 += 16) {
        float4 pv = *(const float4*)(Prow + k0);
        Ps[ak + 0][ar] = pv.x; Ps[ak + 1][ar] = pv.y; Ps[ak + 2][ar] = pv.z; Ps[ak + 3][ar] = pv.w;
        float4 vv = *(const float4*)&V[vbase + (size_t)k0 * DM];
        *(float4*)&Vs[br_][bc] = vv;
        __syncthreads();
#pragma unroll
        for (int kk = 0; kk < 16; kk++) {
            float4 a4 = *(float4*)&Ps[kk][ty * 4];
            float4 b4 = *(float4*)&Vs[kk][tx * 4];
            float ra[4] = {a4.x, a4.y, a4.z, a4.w};
            float rb[4] = {b4.x, b4.y, b4.z, b4.w};
#pragma unroll
            for (int i = 0; i < 4; i++)
#pragma unroll
                for (int j = 0; j < 4; j++) acc[i][j] += ra[i] * rb[j];
        }
        __syncthreads();
    }
#pragma unroll
    for (int i = 0; i < 4; i++)
#pragma unroll
        for (int j = 0; j < 4; j++)
            g_attn[(size_t)(b * SEQ + q0 + ty * 4 + i) * DM + h * HD + tx * 4 + j] = acc[i][j];
}

// ---------------- router ----------------
__global__ void router_kernel(const float* __restrict__ Wr, const float* __restrict__ br) {
    int t = blockIdx.x, tid = threadIdx.x;  // 64 threads
    float acc[NEXP] = {};
    const float* xr = g_xn2 + (size_t)t * DM;
    for (int d = tid; d < DM; d += 64) {
        float xv = xr[d];
        const float* w = Wr + (size_t)d * NEXP;
#pragma unroll
        for (int e = 0; e < NEXP; e++) acc[e] += xv * w[e];
    }
    __shared__ float sh[64][NEXP + 1];
#pragma unroll
    for (int e = 0; e < NEXP; e++) sh[tid][e] = acc[e];
    __syncthreads();
    if (tid < NEXP) {
        float s = br[tid];
        for (int i = 0; i < 64; i++) s += sh[i][tid];
        sh[0][tid] = s;
    }
    __syncthreads();
    if (tid == 0) {
        float l[NEXP];
#pragma unroll
        for (int e = 0; e < NEXP; e++) l[e] = sh[0][e];
        int i1 = 0;
        for (int e = 1; e < NEXP; e++) if (l[e] > l[i1]) i1 = e;
        int i2 = (i1 == 0) ? 1 : 0;
        for (int e = 0; e < NEXP; e++) if (e != i1 && l[e] > l[i2]) i2 = e;
        float g1 = 1.0f / (1.0f + expf(l[i2] - l[i1]));
        float g2 = 1.0f - g1;
        g_top_e[2 * t] = i1; g_top_g[2 * t] = g1;
        g_top_e[2 * t + 1] = i2; g_top_g[2 * t + 1] = g2;
        atomicAdd(&g_cnt[i1], 1);
        atomicAdd(&g_cnt[i2], 1);
    }
}

__global__ void offsets_kernel() {
    if (threadIdx.x == 0) {
        int acc = 0;
#pragma unroll
        for (int e = 0; e < NEXP; e++) { g_off[e] = acc; acc += g_cnt[e]; }
    }
}

__global__ void scatter_kernel() {
    int i = blockIdx.x * 256 + threadIdx.x;
    if (i >= NSLOTS) return;
    int e = g_top_e[i];
    int p = atomicAdd(&g_fill[e], 1);
    int slot = g_off[e] + p;
    g_slot_tok[slot] = i >> 1;
    g_slot_gate[slot] = g_top_g[i];
}

// ---------------- launch ----------------
extern "C" void kernel_launch(void* const* d_in, const int* in_sizes, int n_in,
                              void* d_out, int out_size) {
    const float* x     = (const float*)d_in[0];
    const float* ln1_g = (const float*)d_in[1];
    const float* ln1_b = (const float*)d_in[2];
    const float* Wq    = (const float*)d_in[3];
    const float* Wk    = (const float*)d_in[4];
    const float* Wv    = (const float*)d_in[5];
    const float* Wo    = (const float*)d_in[6];
    const float* bo    = (const float*)d_in[7];
    const float* ln2_g = (const float*)d_in[8];
    const float* ln2_b = (const float*)d_in[9];
    const float* Wr    = (const float*)d_in[10];
    const float* br    = (const float*)d_in[11];
    const float* W1    = (const float*)d_in[12];
    const float* b1    = (const float*)d_in[13];
    const float* W2    = (const float*)d_in[14];
    const float* b2    = (const float*)d_in[15];
    float* out = (float*)d_out;

    float *xn1_p, *q_p, *k_p, *v_p, *attn_p, *xn2_p;
    cudaGetSymbolAddress((void**)&xn1_p, g_xn1);
    cudaGetSymbolAddress((void**)&q_p, g_q);
    cudaGetSymbolAddress((void**)&k_p, g_k);
    cudaGetSymbolAddress((void**)&v_p, g_v);
    cudaGetSymbolAddress((void**)&attn_p, g_attn);
    cudaGetSymbolAddress((void**)&xn2_p, g_xn2);

    zero_cnt_kernel<<<1, 32>>>();
    ln_kernel<<<TOKENS, 256>>>(x, ln1_g, ln1_b, xn1_p);

    dim3 gproj(DM / 128, TOKENS / 128);  // (6, 16)
    bgemm<0><<<gproj, 256>>>(xn1_p, Wq, nullptr, nullptr, q_p, DM, DM);
    bgemm<0><<<gproj, 256>>>(xn1_p, Wk, nullptr, nullptr, k_p, DM, DM);
    bgemm<0><<<gproj, 256>>>(xn1_p, Wv, nullptr, nullptr, v_p, DM, DM);

    attn_scores_kernel<<<dim3(SEQ / 64, SEQ / 64, BH), 256>>>(q_p, k_p);
    softmax_kernel<<<dim3(SEQ, BH), 256>>>();
    attn_av_kernel<<<dim3(1, SEQ / 64, BH), 256>>>(v_p);

    // h = x + attn @ Wo + bo, written DIRECTLY into d_out
    bgemm<1><<<gproj, 256>>>(attn_p, Wo, bo, x, out, DM, DM);

    ln_kernel<<<TOKENS, 256>>>(out, ln2_g, ln2_b, xn2_p);

    router_kernel<<<TOKENS, 64>>>(Wr, br);
    offsets_kernel<<<1, 32>>>();
    scatter_kernel<<<(NSLOTS + 255) / 256, 256>>>();

    bgemm<2><<<dim3(DFF / 128, TOKENS / 128, NEXP), 256>>>(nullptr, W1, b1, nullptr, nullptr, DFF, DM);
    bgemm<3><<<dim3(DM / 128, TOKENS / 128, NEXP), 256>>>(nullptr, W2, b2, nullptr, out, DM, DFF);
}

// round 7
// speedup vs baseline: 2.6094x; 1.1125x over previous
#include <cuda_runtime.h>
#include <cuda_bf16.h>
#include <stdint.h>
#include <stddef.h>
#include <math.h>

#define TOKENS 2048
#define DM 768
#define DFF 3072
#define NEXP 8
#define SEQ 1024
#define NH 12
#define BH 24
#define HD 64
#define NSLOTS (2 * TOKENS)

// ---------------- scratch (static device globals; no allocations) ----------------
__device__ float g_xn1[TOKENS * DM];
__device__ float g_q[TOKENS * DM];
__device__ float g_k[TOKENS * DM];
__device__ float g_v[TOKENS * DM];
__device__ float g_scores[(size_t)BH * SEQ * SEQ];        // 96 MB
__device__ float g_attn[TOKENS * DM];
__device__ float g_xn2[TOKENS * DM];
__device__ unsigned short g_hbuf[(size_t)NSLOTS * DFF];   // 25 MB expert hidden (bf16 bits)
__device__ int   g_cnt[NEXP];
__device__ int   g_off[NEXP];
__device__ int   g_fill[NEXP];
__device__ int   g_top_e[NSLOTS];
__device__ float g_top_g[NSLOTS];
__device__ int   g_slot_tok[NSLOTS];
__device__ float g_slot_gate[NSLOTS];

// ---------------- small helpers ----------------
__global__ void zero_cnt_kernel() {
    int t = threadIdx.x;
    if (t < NEXP) { g_cnt[t] = 0; g_fill[t] = 0; }
}

__device__ __forceinline__ uint32_t smem_u32(const void* p) {
    return (uint32_t)__cvta_generic_to_shared(p);
}
__device__ __forceinline__ uint32_t packbf(float x, float y) {
    __nv_bfloat162 h = __floats2bfloat162_rn(x, y);
    return *(uint32_t*)&h;
}
__device__ __forceinline__ void ldsm_x4(uint32_t& r0, uint32_t& r1, uint32_t& r2, uint32_t& r3, uint32_t addr) {
    asm volatile("ldmatrix.sync.aligned.m8n8.x4.shared.b16 {%0,%1,%2,%3}, [%4];"
                 : "=r"(r0), "=r"(r1), "=r"(r2), "=r"(r3) : "r"(addr));
}
__device__ __forceinline__ void ldsm_x4_t(uint32_t& r0, uint32_t& r1, uint32_t& r2, uint32_t& r3, uint32_t addr) {
    asm volatile("ldmatrix.sync.aligned.m8n8.x4.trans.shared.b16 {%0,%1,%2,%3}, [%4];"
                 : "=r"(r0), "=r"(r1), "=r"(r2), "=r"(r3) : "r"(addr));
}
__device__ __forceinline__ void mma_bf16(float* c, uint32_t a0, uint32_t a1, uint32_t a2, uint32_t a3,
                                         uint32_t b0, uint32_t b1) {
    asm volatile("mma.sync.aligned.m16n8k16.row.col.f32.bf16.bf16.f32 "
                 "{%0,%1,%2,%3},{%4,%5,%6,%7},{%8,%9},{%0,%1,%2,%3};"
                 : "+f"(c[0]), "+f"(c[1]), "+f"(c[2]), "+f"(c[3])
                 : "r"(a0), "r"(a1), "r"(a2), "r"(a3), "r"(b0), "r"(b1));
}
__device__ __forceinline__ float gelu_exact(float x) {
    return 0.5f * x * (1.0f + erff(x * 0.70710678118654752f));
}

// ---------------- bf16 tensor-core GEMM (software-pipelined, double-buffered) ----
// MODE 0: C = A @ B
// MODE 1: C = A @ B + bias + res                     (o-proj)
// MODE 2: hbuf = gelu(gather(xn2) @ W1[e] + b1[e])   (per-expert, bf16 store)
// MODE 3: out[tok] += gate * (hbuf @ W2[e] + b2[e])  (per-expert, atomic)
// MODE 4: fused QKV: {g_q,g_k,g_v} = g_xn1 @ {Wq,Wk,Wv}  (Bw=Wq, bias=Wk, res=Wv)
// CTA: 128x128 tile, BK=32, 256 threads (8 warps, 2x4 -> 64x32 warp tiles)
template<int MODE>
__global__ __launch_bounds__(256)
void bgemm(const float* __restrict__ A, const float* __restrict__ Bw,
           const float* __restrict__ bias, const float* __restrict__ res,
           float* __restrict__ C, int N, int Kdim) {
    int e = (MODE == 2 || MODE == 3) ? blockIdx.z : 0;
    int cnt = 0, off = 0;
    if (MODE == 2 || MODE == 3) {
        cnt = g_cnt[e];
        off = g_off[e];
        if ((int)blockIdx.y * 128 >= cnt) return;
    }
    const float* Bp = Bw;
    if (MODE == 2) Bp += (size_t)e * DM * DFF;
    if (MODE == 3) Bp += (size_t)e * DFF * DM;

    int m00 = blockIdx.y * 128;
    int col0 = blockIdx.x * 128;
    float* outp = C;
    if (MODE == 4) {
        int seg = blockIdx.x / 6;
        Bp = (seg == 0) ? Bw : (seg == 1) ? bias : res;
        outp = (seg == 0) ? g_q : (seg == 1) ? g_k : g_v;
        col0 = (blockIdx.x % 6) * 128;
    }

    __shared__ unsigned short As[2][128][40];   // bf16 bits, padded pitch
    __shared__ unsigned short Bs[2][32][136];

    int tid = threadIdx.x, lane = tid & 31, warp = tid >> 5;
    int wm = (warp & 1) * 64, wn = (warp >> 1) * 32;

    // A loader: thread -> (row = tid>>1, kchunk = (tid&1)*16)
    int ar = tid >> 1, akc = (tid & 1) * 16;
    // B loader: thread -> (krow = tid>>3, col = (tid&7)*16)
    int bkr = tid >> 3, bc = (tid & 7) * 16;

    bool aval = true;
    const float* arow = nullptr;
    const unsigned short* arow16 = nullptr;
    if (MODE <= 1) {
        arow = A + (size_t)(m00 + ar) * Kdim;
    } else if (MODE == 4) {
        arow = g_xn1 + (size_t)(m00 + ar) * DM;
    } else if (MODE == 2) {
        int rc = m00 + ar;
        aval = rc < cnt;
        if (aval) arow = g_xn2 + (size_t)g_slot_tok[off + rc] * DM;
    } else {
        int rc = m00 + ar;
        aval = rc < cnt;
        if (aval) arow16 = g_hbuf + (size_t)(off + rc) * DFF;
    }
    const float* brow = Bp + (size_t)bkr * N + col0 + bc;

    float acc[4][4][4] = {};

    // register staging for prefetch
    uint4 sa0, sa1;      // packed bf16 A (4+4 x bf162 each)
    uint4 sb0, sb1;      // packed bf16 B

    // ---- prefetch helpers (expanded inline) ----
#define LOAD_A_REGS(K0)                                                          \
    do {                                                                         \
        if (MODE == 3) {                                                         \
            if (aval) {                                                          \
                sa0 = *(const uint4*)(arow16 + (K0) + akc);                      \
                sa1 = *(const uint4*)(arow16 + (K0) + akc + 8);                  \
            } else { sa0 = make_uint4(0u,0u,0u,0u); sa1 = sa0; }                 \
        } else {                                                                 \
            if (aval) {                                                          \
                const float* s_ = arow + (K0) + akc;                             \
                float4 v0 = *(const float4*)(s_ + 0);                            \
                float4 v1 = *(const float4*)(s_ + 4);                            \
                float4 v2 = *(const float4*)(s_ + 8);                            \
                float4 v3 = *(const float4*)(s_ + 12);                           \
                sa0 = make_uint4(packbf(v0.x, v0.y), packbf(v0.z, v0.w),         \
                                 packbf(v1.x, v1.y), packbf(v1.z, v1.w));        \
                sa1 = make_uint4(packbf(v2.x, v2.y), packbf(v2.z, v2.w),         \
                                 packbf(v3.x, v3.y), packbf(v3.z, v3.w));        \
            } else { sa0 = make_uint4(0u,0u,0u,0u); sa1 = sa0; }                 \
        }                                                                        \
    } while (0)

#define LOAD_B_REGS(K0)                                                          \
    do {                                                                         \
        const float* s_ = brow + (size_t)(K0) * N;                               \
        float4 w0 = *(const float4*)(s_ + 0);                                    \
        float4 w1 = *(const float4*)(s_ + 4);                                    \
        float4 w2 = *(const float4*)(s_ + 8);                                    \
        float4 w3 = *(const float4*)(s_ + 12);                                   \
        sb0 = make_uint4(packbf(w0.x, w0.y), packbf(w0.z, w0.w),                 \
                         packbf(w1.x, w1.y), packbf(w1.z, w1.w));                \
        sb1 = make_uint4(packbf(w2.x, w2.y), packbf(w2.z, w2.w),                 \
                         packbf(w3.x, w3.y), packbf(w3.z, w3.w));                \
    } while (0)

#define STORE_TILE(BUF)                                                          \
    do {                                                                         \
        *(uint4*)&As[BUF][ar][akc] = sa0;                                        \
        *(uint4*)&As[BUF][ar][akc + 8] = sa1;                                    \
        *(uint4*)&Bs[BUF][bkr][bc] = sb0;                                        \
        *(uint4*)&Bs[BUF][bkr][bc + 8] = sb1;                                    \
    } while (0)

    // prologue: tile 0 -> buffer 0
    LOAD_A_REGS(0);
    LOAD_B_REGS(0);
    STORE_TILE(0);
    __syncthreads();

    int nIter = Kdim >> 5;
    int buf = 0;
    for (int it = 0; it < nIter; it++) {
        int knext = (it + 1) << 5;
        bool have_next = knext < Kdim;
        if (have_next) {
            LOAD_A_REGS(knext);
            LOAD_B_REGS(knext);
        }

        // compute from As[buf]/Bs[buf]
#pragma unroll
        for (int ks = 0; ks < 2; ks++) {
            int kk = ks * 16;
            uint32_t a[4][4];
#pragma unroll
            for (int mi = 0; mi < 4; mi++) {
                uint32_t addr = smem_u32(&As[buf][wm + mi * 16 + (lane & 15)][kk + (lane >> 4) * 8]);
                ldsm_x4(a[mi][0], a[mi][1], a[mi][2], a[mi][3], addr);
            }
            uint32_t b[4][2];
#pragma unroll
            for (int nb = 0; nb < 2; nb++) {
                uint32_t addr = smem_u32(&Bs[buf][kk + (lane & 15)][wn + nb * 16 + (lane >> 4) * 8]);
                ldsm_x4_t(b[nb * 2][0], b[nb * 2][1], b[nb * 2 + 1][0], b[nb * 2 + 1][1], addr);
            }
#pragma unroll
            for (int mi = 0; mi < 4; mi++)
#pragma unroll
                for (int nj = 0; nj < 4; nj++)
                    mma_bf16(acc[mi][nj], a[mi][0], a[mi][1], a[mi][2], a[mi][3],
                             b[nj][0], b[nj][1]);
        }

        if (have_next) STORE_TILE(buf ^ 1);
        __syncthreads();
        buf ^= 1;
    }

    // ---- epilogue ----
    int g = lane >> 2, t4 = lane & 3;
#pragma unroll
    for (int mi = 0; mi < 4; mi++) {
#pragma unroll
        for (int h2 = 0; h2 < 2; h2++) {
            int rloc = wm + mi * 16 + g + h2 * 8;
            if (MODE == 2 || MODE == 3) {
                int rc = m00 + rloc;
                if (rc >= cnt) continue;
                int slot = off + rc;
                if (MODE == 2) {
                    size_t base = (size_t)slot * DFF;
#pragma unroll
                    for (int nj = 0; nj < 4; nj++) {
                        int col = col0 + wn + nj * 8 + 2 * t4;
                        float v0 = gelu_exact(acc[mi][nj][h2 * 2 + 0] + bias[(size_t)e * DFF + col]);
                        float v1 = gelu_exact(acc[mi][nj][h2 * 2 + 1] + bias[(size_t)e * DFF + col + 1]);
                        uint32_t p = packbf(v0, v1);
                        *(uint32_t*)&g_hbuf[base + col] = p;
                    }
                } else {
                    int tok = g_slot_tok[slot];
                    float gt = g_slot_gate[slot];
#pragma unroll
                    for (int nj = 0; nj < 4; nj++) {
                        int col = col0 + wn + nj * 8 + 2 * t4;
                        float v0 = (acc[mi][nj][h2 * 2 + 0] + bias[(size_t)e * DM + col]) * gt;
                        float v1 = (acc[mi][nj][h2 * 2 + 1] + bias[(size_t)e * DM + col + 1]) * gt;
                        atomicAdd(&C[(size_t)tok * DM + col], v0);
                        atomicAdd(&C[(size_t)tok * DM + col + 1], v1);
                    }
                }
            } else {
                int row = m00 + rloc;
#pragma unroll
                for (int nj = 0; nj < 4; nj++) {
                    int col = col0 + wn + nj * 8 + 2 * t4;
                    float v0 = acc[mi][nj][h2 * 2 + 0];
                    float v1 = acc[mi][nj][h2 * 2 + 1];
                    if (MODE == 1) {
                        v0 += bias[col] + res[(size_t)row * N + col];
                        v1 += bias[col + 1] + res[(size_t)row * N + col + 1];
                    }
                    *(float2*)&outp[(size_t)row * N + col] = make_float2(v0, v1);
                }
            }
        }
    }
#undef LOAD_A_REGS
#undef LOAD_B_REGS
#undef STORE_TILE
}

// ---------------- layernorm (one block per token row) ----------------
__global__ void ln_kernel(const float* __restrict__ x, const float* __restrict__ gam,
                          const float* __restrict__ bet, float* __restrict__ y) {
    int row = blockIdx.x;
    int tid = threadIdx.x;  // 256
    __shared__ float sx[DM];
    __shared__ float red[256];
    const float* xr = x + (size_t)row * DM;
    float s = 0.f;
    for (int i = tid; i < DM; i += 256) { float v = xr[i]; sx[i] = v; s += v; }
    red[tid] = s; __syncthreads();
    for (int o = 128; o > 0; o >>= 1) { if (tid < o) red[tid] += red[tid + o]; __syncthreads(); }
    float m = red[0] * (1.0f / DM);
    __syncthreads();
    float s2 = 0.f;
    for (int i = tid; i < DM; i += 256) { float d = sx[i] - m; s2 += d * d; }
    red[tid] = s2; __syncthreads();
    for (int o = 128; o > 0; o >>= 1) { if (tid < o) red[tid] += red[tid + o]; __syncthreads(); }
    float var = red[0] * (1.0f / DM);
    float r = rsqrtf(var + 1e-5f);
    for (int i = tid; i < DM; i += 256)
        y[(size_t)row * DM + i] = (sx[i] - m) * r * gam[i] + bet[i];
}

// ---------------- attention scores: S = Q Kt * 0.125 (causal tiles only) ----------------
__global__ void attn_scores_kernel(const float* __restrict__ Q, const float* __restrict__ Km) {
    int bh = blockIdx.z; int b = bh / NH, h = bh % NH;
    int qt = blockIdx.y, kt = blockIdx.x;
    if (kt > qt) return;
    int q0 = qt * 64, k0 = kt * 64;
    __shared__ float Qs[64][68];
    __shared__ float Ks[64][68];
    int tid = threadIdx.x;
    int lr = tid & 15, rr = tid >> 4;
    size_t base_q = (size_t)(b * SEQ + q0) * DM + h * HD;
    size_t base_k = (size_t)(b * SEQ + k0) * DM + h * HD;
#pragma unroll
    for (int c = 0; c < 4; c++) {
        int r = rr + 16 * c;
        float4 qv = *(const float4*)&Q[base_q + (size_t)r * DM + lr * 4];
        Qs[lr * 4 + 0][r] = qv.x; Qs[lr * 4 + 1][r] = qv.y; Qs[lr * 4 + 2][r] = qv.z; Qs[lr * 4 + 3][r] = qv.w;
        float4 kv = *(const float4*)&Km[base_k + (size_t)r * DM + lr * 4];
        Ks[lr * 4 + 0][r] = kv.x; Ks[lr * 4 + 1][r] = kv.y; Ks[lr * 4 + 2][r] = kv.z; Ks[lr * 4 + 3][r] = kv.w;
    }
    __syncthreads();
    int tx = tid & 15, ty = tid >> 4;
    float acc[4][4] = {};
#pragma unroll 8
    for (int d = 0; d < 64; d++) {
        float4 a4 = *(float4*)&Qs[d][ty * 4];
        float4 b4 = *(float4*)&Ks[d][tx * 4];
        float ra[4] = {a4.x, a4.y, a4.z, a4.w};
        float rb[4] = {b4.x, b4.y, b4.z, b4.w};
#pragma unroll
        for (int i = 0; i < 4; i++)
#pragma unroll
            for (int j = 0; j < 4; j++) acc[i][j] += ra[i] * rb[j];
    }
    float* out = g_scores + (size_t)bh * SEQ * SEQ;
#pragma unroll
    for (int i = 0; i < 4; i++)
#pragma unroll
        for (int j = 0; j < 4; j++)
            out[(size_t)(q0 + ty * 4 + i) * SEQ + k0 + tx * 4 + j] = acc[i][j] * 0.125f;
}

// ---------------- causal row softmax ----------------
__global__ void softmax_kernel() {
    int q = blockIdx.x, bh = blockIdx.y;
    float* row = g_scores + (size_t)bh * SEQ * SEQ + (size_t)q * SEQ;
    int n = q + 1, tid = threadIdx.x;
    __shared__ float red[256];
    float m = -1e30f;
    for (int i = tid; i < n; i += 256) m = fmaxf(m, row[i]);
    red[tid] = m; __syncthreads();
    for (int o = 128; o > 0; o >>= 1) { if (tid < o) red[tid] = fmaxf(red[tid], red[tid + o]); __syncthreads(); }
    m = red[0]; __syncthreads();
    float s = 0.f;
    for (int i = tid; i < n; i += 256) s += expf(row[i] - m);
    red[tid] = s; __syncthreads();
    for (int o = 128; o > 0; o >>= 1) { if (tid < o) red[tid] += red[tid + o]; __syncthreads(); }
    float inv = 1.0f / red[0];
    for (int i = tid; i < n; i += 256) row[i] = expf(row[i] - m) * inv;
    for (int i = n + tid; i < SEQ; i += 256) row[i] = 0.0f;
}

// ---------------- attention output: O = P @ V ----------------
__global__ void attn_av_kernel(const float* __restrict__ V) {
    int bh = blockIdx.z; int b = bh / NH, h = bh % NH;
    int q0 = blockIdx.y * 64;
    __shared__ float Ps[16][68];
    __shared__ float Vs[16][68];
    int tid = threadIdx.x;
    int ar = tid >> 2, ak = (tid & 3) * 4;
    int br_ = tid >> 4, bc = (tid & 15) * 4;
    int tx = tid & 15, ty = tid >> 4;
    const float* Prow = g_scores + (size_t)bh * SEQ * SEQ + (size_t)(q0 + ar) * SEQ + ak;
    size_t vbase = (size_t)(b * SEQ + br_) * DM + h * HD + bc;
    float acc[4][4] = {};
    int kmax = q0 + 64;
    for (int k0 = 0; k0 < kmax; k0 += 16) {
        float4 pv = *(const float4*)(Prow + k0);
        Ps[ak + 0][ar] = pv.x; Ps[ak + 1][ar] = pv.y; Ps[ak + 2][ar] = pv.z; Ps[ak + 3][ar] = pv.w;
        float4 vv = *(const float4*)&V[vbase + (size_t)k0 * DM];
        *(float4*)&Vs[br_][bc] = vv;
        __syncthreads();
#pragma unroll
        for (int kk = 0; kk < 16; kk++) {
            float4 a4 = *(float4*)&Ps[kk][ty * 4];
            float4 b4 = *(float4*)&Vs[kk][tx * 4];
            float ra[4] = {a4.x, a4.y, a4.z, a4.w};
            float rb[4] = {b4.x, b4.y, b4.z, b4.w};
#pragma unroll
            for (int i = 0; i < 4; i++)
#pragma unroll
                for (int j = 0; j < 4; j++) acc[i][j] += ra[i] * rb[j];
        }
        __syncthreads();
    }
#pragma unroll
    for (int i = 0; i < 4; i++)
#pragma unroll
        for (int j = 0; j < 4; j++)
            g_attn[(size_t)(b * SEQ + q0 + ty * 4 + i) * DM + h * HD + tx * 4 + j] = acc[i][j];
}

// ---------------- router ----------------
__global__ void router_kernel(const float* __restrict__ Wr, const float* __restrict__ br) {
    int t = blockIdx.x, tid = threadIdx.x;  // 64 threads
    float acc[NEXP] = {};
    const float* xr = g_xn2 + (size_t)t * DM;
    for (int d = tid; d < DM; d += 64) {
        float xv = xr[d];
        const float* w = Wr + (size_t)d * NEXP;
#pragma unroll
        for (int e = 0; e < NEXP; e++) acc[e] += xv * w[e];
    }
    __shared__ float sh[64][NEXP + 1];
#pragma unroll
    for (int e = 0; e < NEXP; e++) sh[tid][e] = acc[e];
    __syncthreads();
    if (tid < NEXP) {
        float s = br[tid];
        for (int i = 0; i < 64; i++) s += sh[i][tid];
        sh[0][tid] = s;
    }
    __syncthreads();
    if (tid == 0) {
        float l[NEXP];
#pragma unroll
        for (int e = 0; e < NEXP; e++) l[e] = sh[0][e];
        int i1 = 0;
        for (int e = 1; e < NEXP; e++) if (l[e] > l[i1]) i1 = e;
        int i2 = (i1 == 0) ? 1 : 0;
        for (int e = 0; e < NEXP; e++) if (e != i1 && l[e] > l[i2]) i2 = e;
        float g1 = 1.0f / (1.0f + expf(l[i2] - l[i1]));
        float g2 = 1.0f - g1;
        g_top_e[2 * t] = i1; g_top_g[2 * t] = g1;
        g_top_e[2 * t + 1] = i2; g_top_g[2 * t + 1] = g2;
        atomicAdd(&g_cnt[i1], 1);
        atomicAdd(&g_cnt[i2], 1);
    }
}

__global__ void offsets_kernel() {
    if (threadIdx.x == 0) {
        int acc = 0;
#pragma unroll
        for (int e = 0; e < NEXP; e++) { g_off[e] = acc; acc += g_cnt[e]; }
    }
}

__global__ void scatter_kernel() {
    int i = blockIdx.x * 256 + threadIdx.x;
    if (i >= NSLOTS) return;
    int e = g_top_e[i];
    int p = atomicAdd(&g_fill[e], 1);
    int slot = g_off[e] + p;
    g_slot_tok[slot] = i >> 1;
    g_slot_gate[slot] = g_top_g[i];
}

// ---------------- launch ----------------
extern "C" void kernel_launch(void* const* d_in, const int* in_sizes, int n_in,
                              void* d_out, int out_size) {
    const float* x     = (const float*)d_in[0];
    const float* ln1_g = (const float*)d_in[1];
    const float* ln1_b = (const float*)d_in[2];
    const float* Wq    = (const float*)d_in[3];
    const float* Wk    = (const float*)d_in[4];
    const float* Wv    = (const float*)d_in[5];
    const float* Wo    = (const float*)d_in[6];
    const float* bo    = (const float*)d_in[7];
    const float* ln2_g = (const float*)d_in[8];
    const float* ln2_b = (const float*)d_in[9];
    const float* Wr    = (const float*)d_in[10];
    const float* br    = (const float*)d_in[11];
    const float* W1    = (const float*)d_in[12];
    const float* b1    = (const float*)d_in[13];
    const float* W2    = (const float*)d_in[14];
    const float* b2    = (const float*)d_in[15];
    float* out = (float*)d_out;

    float *xn1_p, *q_p, *k_p, *v_p, *attn_p, *xn2_p;
    cudaGetSymbolAddress((void**)&xn1_p, g_xn1);
    cudaGetSymbolAddress((void**)&q_p, g_q);
    cudaGetSymbolAddress((void**)&k_p, g_k);
    cudaGetSymbolAddress((void**)&v_p, g_v);
    cudaGetSymbolAddress((void**)&attn_p, g_attn);
    cudaGetSymbolAddress((void**)&xn2_p, g_xn2);

    zero_cnt_kernel<<<1, 32>>>();
    ln_kernel<<<TOKENS, 256>>>(x, ln1_g, ln1_b, xn1_p);

    // fused QKV: 18 x 16 = 288 CTAs, one launch
    bgemm<4><<<dim3(18, TOKENS / 128), 256>>>(nullptr, Wq, Wk, Wv, nullptr, DM, DM);

    attn_scores_kernel<<<dim3(SEQ / 64, SEQ / 64, BH), 256>>>(q_p, k_p);
    softmax_kernel<<<dim3(SEQ, BH), 256>>>();
    attn_av_kernel<<<dim3(1, SEQ / 64, BH), 256>>>(v_p);

    // h = x + attn @ Wo + bo, written DIRECTLY into d_out
    bgemm<1><<<dim3(DM / 128, TOKENS / 128), 256>>>(attn_p, Wo, bo, x, out, DM, DM);

    ln_kernel<<<TOKENS, 256>>>(out, ln2_g, ln2_b, xn2_p);

    router_kernel<<<TOKENS, 64>>>(Wr, br);
    offsets_kernel<<<1, 32>>>();
    scatter_kernel<<<(NSLOTS + 255) / 256, 256>>>();

    bgemm<2><<<dim3(DFF / 128, TOKENS / 128, NEXP), 256>>>(nullptr, W1, b1, nullptr, nullptr, DFF, DM);
    bgemm<3><<<dim3(DM / 128, TOKENS / 128, NEXP), 256>>>(nullptr, W2, b2, nullptr, out, DM, DFF);
}

// round 8
// speedup vs baseline: 3.5010x; 1.3417x over previous
#include <cuda_runtime.h>
#include <cuda_bf16.h>
#include <stdint.h>
#include <stddef.h>
#include <math.h>

#define TOKENS 2048
#define DM 768
#define DFF 3072
#define NEXP 8
#define SEQ 1024
#define NH 12
#define BH 24
#define HD 64
#define NSLOTS (2 * TOKENS)

// ---------------- scratch (static device globals; no allocations) ----------------
__device__ float g_xn1[TOKENS * DM];
__device__ float g_q[TOKENS * DM];
__device__ float g_k[TOKENS * DM];
__device__ float g_v[TOKENS * DM];
__device__ float g_attn[TOKENS * DM];
__device__ float g_xn2[TOKENS * DM];
__device__ unsigned short g_hbuf[(size_t)NSLOTS * DFF];   // 25 MB expert hidden (bf16 bits)
__device__ int   g_cnt[NEXP];
__device__ int   g_off[NEXP];
__device__ int   g_fill[NEXP];
__device__ int   g_top_e[NSLOTS];
__device__ float g_top_g[NSLOTS];
__device__ int   g_slot_tok[NSLOTS];
__device__ float g_slot_gate[NSLOTS];

// ---------------- small helpers ----------------
__global__ void zero_cnt_kernel() {
    int t = threadIdx.x;
    if (t < NEXP) { g_cnt[t] = 0; g_fill[t] = 0; }
}

__device__ __forceinline__ uint32_t smem_u32(const void* p) {
    return (uint32_t)__cvta_generic_to_shared(p);
}
__device__ __forceinline__ uint32_t packbf(float x, float y) {
    __nv_bfloat162 h = __floats2bfloat162_rn(x, y);
    return *(uint32_t*)&h;
}
__device__ __forceinline__ void ldsm_x4(uint32_t& r0, uint32_t& r1, uint32_t& r2, uint32_t& r3, uint32_t addr) {
    asm volatile("ldmatrix.sync.aligned.m8n8.x4.shared.b16 {%0,%1,%2,%3}, [%4];"
                 : "=r"(r0), "=r"(r1), "=r"(r2), "=r"(r3) : "r"(addr));
}
__device__ __forceinline__ void ldsm_x4_t(uint32_t& r0, uint32_t& r1, uint32_t& r2, uint32_t& r3, uint32_t addr) {
    asm volatile("ldmatrix.sync.aligned.m8n8.x4.trans.shared.b16 {%0,%1,%2,%3}, [%4];"
                 : "=r"(r0), "=r"(r1), "=r"(r2), "=r"(r3) : "r"(addr));
}
__device__ __forceinline__ void mma_bf16(float* c, uint32_t a0, uint32_t a1, uint32_t a2, uint32_t a3,
                                         uint32_t b0, uint32_t b1) {
    asm volatile("mma.sync.aligned.m16n8k16.row.col.f32.bf16.bf16.f32 "
                 "{%0,%1,%2,%3},{%4,%5,%6,%7},{%8,%9},{%0,%1,%2,%3};"
                 : "+f"(c[0]), "+f"(c[1]), "+f"(c[2]), "+f"(c[3])
                 : "r"(a0), "r"(a1), "r"(a2), "r"(a3), "r"(b0), "r"(b1));
}
__device__ __forceinline__ float gelu_exact(float x) {
    return 0.5f * x * (1.0f + erff(x * 0.70710678118654752f));
}

// ---------------- bf16 tensor-core GEMM (software-pipelined, double-buffered) ----
// MODE 0: C = A @ B
// MODE 1: C = A @ B + bias + res                     (o-proj)
// MODE 2: hbuf = gelu(gather(xn2) @ W1[e] + b1[e])   (per-expert, bf16 store)
// MODE 3: out[tok] += gate * (hbuf @ W2[e] + b2[e])  (per-expert, atomic)
// MODE 4: fused QKV: {g_q,g_k,g_v} = g_xn1 @ {Wq,Wk,Wv}  (Bw=Wq, bias=Wk, res=Wv)
template<int MODE>
__global__ __launch_bounds__(256)
void bgemm(const float* __restrict__ A, const float* __restrict__ Bw,
           const float* __restrict__ bias, const float* __restrict__ res,
           float* __restrict__ C, int N, int Kdim) {
    int e = (MODE == 2 || MODE == 3) ? blockIdx.z : 0;
    int cnt = 0, off = 0;
    if (MODE == 2 || MODE == 3) {
        cnt = g_cnt[e];
        off = g_off[e];
        if ((int)blockIdx.y * 128 >= cnt) return;
    }
    const float* Bp = Bw;
    if (MODE == 2) Bp += (size_t)e * DM * DFF;
    if (MODE == 3) Bp += (size_t)e * DFF * DM;

    int m00 = blockIdx.y * 128;
    int col0 = blockIdx.x * 128;
    float* outp = C;
    if (MODE == 4) {
        int seg = blockIdx.x / 6;
        Bp = (seg == 0) ? Bw : (seg == 1) ? bias : res;
        outp = (seg == 0) ? g_q : (seg == 1) ? g_k : g_v;
        col0 = (blockIdx.x % 6) * 128;
    }

    __shared__ unsigned short As[2][128][40];
    __shared__ unsigned short Bs[2][32][136];

    int tid = threadIdx.x, lane = tid & 31, warp = tid >> 5;
    int wm = (warp & 1) * 64, wn = (warp >> 1) * 32;

    int ar = tid >> 1, akc = (tid & 1) * 16;
    int bkr = tid >> 3, bc = (tid & 7) * 16;

    bool aval = true;
    const float* arow = nullptr;
    const unsigned short* arow16 = nullptr;
    if (MODE <= 1) {
        arow = A + (size_t)(m00 + ar) * Kdim;
    } else if (MODE == 4) {
        arow = g_xn1 + (size_t)(m00 + ar) * DM;
    } else if (MODE == 2) {
        int rc = m00 + ar;
        aval = rc < cnt;
        if (aval) arow = g_xn2 + (size_t)g_slot_tok[off + rc] * DM;
    } else {
        int rc = m00 + ar;
        aval = rc < cnt;
        if (aval) arow16 = g_hbuf + (size_t)(off + rc) * DFF;
    }
    const float* brow = Bp + (size_t)bkr * N + col0 + bc;

    float acc[4][4][4] = {};

    uint4 sa0, sa1;
    uint4 sb0, sb1;

#define LOAD_A_REGS(K0)                                                          \
    do {                                                                         \
        if (MODE == 3) {                                                         \
            if (aval) {                                                          \
                sa0 = *(const uint4*)(arow16 + (K0) + akc);                      \
                sa1 = *(const uint4*)(arow16 + (K0) + akc + 8);                  \
            } else { sa0 = make_uint4(0u,0u,0u,0u); sa1 = sa0; }                 \
        } else {                                                                 \
            if (aval) {                                                          \
                const float* s_ = arow + (K0) + akc;                             \
                float4 v0 = *(const float4*)(s_ + 0);                            \
                float4 v1 = *(const float4*)(s_ + 4);                            \
                float4 v2 = *(const float4*)(s_ + 8);                            \
                float4 v3 = *(const float4*)(s_ + 12);                           \
                sa0 = make_uint4(packbf(v0.x, v0.y), packbf(v0.z, v0.w),         \
                                 packbf(v1.x, v1.y), packbf(v1.z, v1.w));        \
                sa1 = make_uint4(packbf(v2.x, v2.y), packbf(v2.z, v2.w),         \
                                 packbf(v3.x, v3.y), packbf(v3.z, v3.w));        \
            } else { sa0 = make_uint4(0u,0u,0u,0u); sa1 = sa0; }                 \
        }                                                                        \
    } while (0)

#define LOAD_B_REGS(K0)                                                          \
    do {                                                                         \
        const float* s_ = brow + (size_t)(K0) * N;                               \
        float4 w0 = *(const float4*)(s_ + 0);                                    \
        float4 w1 = *(const float4*)(s_ + 4);                                    \
        float4 w2 = *(const float4*)(s_ + 8);                                    \
        float4 w3 = *(const float4*)(s_ + 12);                                   \
        sb0 = make_uint4(packbf(w0.x, w0.y), packbf(w0.z, w0.w),                 \
                         packbf(w1.x, w1.y), packbf(w1.z, w1.w));                \
        sb1 = make_uint4(packbf(w2.x, w2.y), packbf(w2.z, w2.w),                 \
                         packbf(w3.x, w3.y), packbf(w3.z, w3.w));                \
    } while (0)

#define STORE_TILE(BUF)                                                          \
    do {                                                                         \
        *(uint4*)&As[BUF][ar][akc] = sa0;                                        \
        *(uint4*)&As[BUF][ar][akc + 8] = sa1;                                    \
        *(uint4*)&Bs[BUF][bkr][bc] = sb0;                                        \
        *(uint4*)&Bs[BUF][bkr][bc + 8] = sb1;                                    \
    } while (0)

    LOAD_A_REGS(0);
    LOAD_B_REGS(0);
    STORE_TILE(0);
    __syncthreads();

    int nIter = Kdim >> 5;
    int buf = 0;
    for (int it = 0; it < nIter; it++) {
        int knext = (it + 1) << 5;
        bool have_next = knext < Kdim;
        if (have_next) {
            LOAD_A_REGS(knext);
            LOAD_B_REGS(knext);
        }

#pragma unroll
        for (int ks = 0; ks < 2; ks++) {
            int kk = ks * 16;
            uint32_t a[4][4];
#pragma unroll
            for (int mi = 0; mi < 4; mi++) {
                uint32_t addr = smem_u32(&As[buf][wm + mi * 16 + (lane & 15)][kk + (lane >> 4) * 8]);
                ldsm_x4(a[mi][0], a[mi][1], a[mi][2], a[mi][3], addr);
            }
            uint32_t b[4][2];
#pragma unroll
            for (int nb = 0; nb < 2; nb++) {
                uint32_t addr = smem_u32(&Bs[buf][kk + (lane & 15)][wn + nb * 16 + (lane >> 4) * 8]);
                ldsm_x4_t(b[nb * 2][0], b[nb * 2][1], b[nb * 2 + 1][0], b[nb * 2 + 1][1], addr);
            }
#pragma unroll
            for (int mi = 0; mi < 4; mi++)
#pragma unroll
                for (int nj = 0; nj < 4; nj++)
                    mma_bf16(acc[mi][nj], a[mi][0], a[mi][1], a[mi][2], a[mi][3],
                             b[nj][0], b[nj][1]);
        }

        if (have_next) STORE_TILE(buf ^ 1);
        __syncthreads();
        buf ^= 1;
    }

    int g = lane >> 2, t4 = lane & 3;
#pragma unroll
    for (int mi = 0; mi < 4; mi++) {
#pragma unroll
        for (int h2 = 0; h2 < 2; h2++) {
            int rloc = wm + mi * 16 + g + h2 * 8;
            if (MODE == 2 || MODE == 3) {
                int rc = m00 + rloc;
                if (rc >= cnt) continue;
                int slot = off + rc;
                if (MODE == 2) {
                    size_t base = (size_t)slot * DFF;
#pragma unroll
                    for (int nj = 0; nj < 4; nj++) {
                        int col = col0 + wn + nj * 8 + 2 * t4;
                        float v0 = gelu_exact(acc[mi][nj][h2 * 2 + 0] + bias[(size_t)e * DFF + col]);
                        float v1 = gelu_exact(acc[mi][nj][h2 * 2 + 1] + bias[(size_t)e * DFF + col + 1]);
                        uint32_t p = packbf(v0, v1);
                        *(uint32_t*)&g_hbuf[base + col] = p;
                    }
                } else {
                    int tok = g_slot_tok[slot];
                    float gt = g_slot_gate[slot];
#pragma unroll
                    for (int nj = 0; nj < 4; nj++) {
                        int col = col0 + wn + nj * 8 + 2 * t4;
                        float v0 = (acc[mi][nj][h2 * 2 + 0] + bias[(size_t)e * DM + col]) * gt;
                        float v1 = (acc[mi][nj][h2 * 2 + 1] + bias[(size_t)e * DM + col + 1]) * gt;
                        atomicAdd(&C[(size_t)tok * DM + col], v0);
                        atomicAdd(&C[(size_t)tok * DM + col + 1], v1);
                    }
                }
            } else {
                int row = m00 + rloc;
#pragma unroll
                for (int nj = 0; nj < 4; nj++) {
                    int col = col0 + wn + nj * 8 + 2 * t4;
                    float v0 = acc[mi][nj][h2 * 2 + 0];
                    float v1 = acc[mi][nj][h2 * 2 + 1];
                    if (MODE == 1) {
                        v0 += bias[col] + res[(size_t)row * N + col];
                        v1 += bias[col + 1] + res[(size_t)row * N + col + 1];
                    }
                    *(float2*)&outp[(size_t)row * N + col] = make_float2(v0, v1);
                }
            }
        }
    }
#undef LOAD_A_REGS
#undef LOAD_B_REGS
#undef STORE_TILE
}

// ---------------- fused flash attention (bf16 HMMA + fp32 online softmax) -------
// grid: (16 q-tiles reversed, BH). 128 threads = 4 warps x 16 q-rows.
// Writes g_attn[b, s, h*64+d] = softmax(QK^T/8, causal) @ V.
__global__ __launch_bounds__(128)
void flash_attn_kernel() {
    int bh = blockIdx.y; int b = bh / NH, h = bh % NH;
    int qt = (int)(gridDim.x - 1) - (int)blockIdx.x;  // heavy tiles first
    int q0 = qt * 64;
    int tid = threadIdx.x, lane = tid & 31, warp = tid >> 5;
    int wq = warp * 16;

    __shared__ unsigned short Qs[64][72];
    __shared__ unsigned short Ks[64][72];
    __shared__ unsigned short Vs[64][72];

    // load Q tile (64x64 fp32 -> bf16). thread: row=tid>>1, 32-col half=tid&1
    {
        int r = tid >> 1, c0 = (tid & 1) * 32;
        const float* src = g_q + (size_t)(b * SEQ + q0 + r) * DM + h * HD + c0;
#pragma unroll
        for (int i = 0; i < 4; i++) {
            float4 va = *(const float4*)(src + i * 8);
            float4 vb = *(const float4*)(src + i * 8 + 4);
            *(uint4*)&Qs[r][c0 + i * 8] = make_uint4(packbf(va.x, va.y), packbf(va.z, va.w),
                                                     packbf(vb.x, vb.y), packbf(vb.z, vb.w));
        }
    }
    __syncthreads();

    // Q fragments: 4 k-chunks of 16, loaded once
    uint32_t qa[4][4];
#pragma unroll
    for (int kc = 0; kc < 4; kc++) {
        uint32_t addr = smem_u32(&Qs[wq + (lane & 15)][kc * 16 + (lane >> 4) * 8]);
        ldsm_x4(qa[kc][0], qa[kc][1], qa[kc][2], qa[kc][3], addr);
    }

    float m_run[2] = {-1e30f, -1e30f};
    float l_run[2] = {0.f, 0.f};
    float oacc[8][4] = {};

    for (int kt = 0; kt <= qt; kt++) {
        int k0 = kt * 64;
        __syncthreads();  // previous iteration's consumers done with Ks/Vs
        {
            int r = tid >> 1, c0 = (tid & 1) * 32;
            const float* ksrc = g_k + (size_t)(b * SEQ + k0 + r) * DM + h * HD + c0;
            const float* vsrc = g_v + (size_t)(b * SEQ + k0 + r) * DM + h * HD + c0;
#pragma unroll
            for (int i = 0; i < 4; i++) {
                float4 va = *(const float4*)(ksrc + i * 8);
                float4 vb = *(const float4*)(ksrc + i * 8 + 4);
                *(uint4*)&Ks[r][c0 + i * 8] = make_uint4(packbf(va.x, va.y), packbf(va.z, va.w),
                                                         packbf(vb.x, vb.y), packbf(vb.z, vb.w));
                va = *(const float4*)(vsrc + i * 8);
                vb = *(const float4*)(vsrc + i * 8 + 4);
                *(uint4*)&Vs[r][c0 + i * 8] = make_uint4(packbf(va.x, va.y), packbf(va.z, va.w),
                                                         packbf(vb.x, vb.y), packbf(vb.z, vb.w));
            }
        }
        __syncthreads();

        // S = Q K^T  (per warp: 16 x 64, k=64)
        float sacc[8][4] = {};
#pragma unroll
        for (int kc = 0; kc < 4; kc++) {
#pragma unroll
            for (int nb = 0; nb < 4; nb++) {
                uint32_t r0, r1, r2, r3;
                uint32_t addr = smem_u32(&Ks[nb * 16 + (lane & 7) + ((lane >> 3) & 1) * 8]
                                           [kc * 16 + (lane >> 4) * 8]);
                ldsm_x4(r0, r1, r2, r3, addr);
                mma_bf16(sacc[nb * 2],     qa[kc][0], qa[kc][1], qa[kc][2], qa[kc][3], r0, r2);
                mma_bf16(sacc[nb * 2 + 1], qa[kc][0], qa[kc][1], qa[kc][2], qa[kc][3], r1, r3);
            }
        }

        // online softmax (fp32), causal mask only on diagonal tile
        bool diag = (kt == qt);
#pragma unroll
        for (int half = 0; half < 2; half++) {
            int qrow = q0 + wq + (lane >> 2) + half * 8;
            float vals[16];
#pragma unroll
            for (int nj = 0; nj < 8; nj++) {
                int colg = k0 + nj * 8 + 2 * (lane & 3);
                float v0 = sacc[nj][half * 2 + 0] * 0.125f;
                float v1 = sacc[nj][half * 2 + 1] * 0.125f;
                if (diag) {
                    if (colg > qrow) v0 = -1e30f;
                    if (colg + 1 > qrow) v1 = -1e30f;
                }
                vals[nj * 2] = v0;
                vals[nj * 2 + 1] = v1;
            }
            float tmx = vals[0];
#pragma unroll
            for (int i = 1; i < 16; i++) tmx = fmaxf(tmx, vals[i]);
            tmx = fmaxf(tmx, __shfl_xor_sync(0xffffffffu, tmx, 1));
            tmx = fmaxf(tmx, __shfl_xor_sync(0xffffffffu, tmx, 2));
            float mnew = fmaxf(m_run[half], tmx);
            float corr = __expf(m_run[half] - mnew);
            float rsum = 0.f;
#pragma unroll
            for (int i = 0; i < 16; i++) {
                float p = __expf(vals[i] - mnew);
                vals[i] = p;
                rsum += p;
            }
            rsum += __shfl_xor_sync(0xffffffffu, rsum, 1);
            rsum += __shfl_xor_sync(0xffffffffu, rsum, 2);
            l_run[half] = l_run[half] * corr + rsum;
            m_run[half] = mnew;
#pragma unroll
            for (int nj = 0; nj < 8; nj++) {
                oacc[nj][half * 2 + 0] *= corr;
                oacc[nj][half * 2 + 1] *= corr;
                sacc[nj][half * 2 + 0] = vals[nj * 2];
                sacc[nj][half * 2 + 1] = vals[nj * 2 + 1];
            }
        }

        // O += P @ V  (P fragments straight from sacc registers)
#pragma unroll
        for (int j = 0; j < 4; j++) {
            uint32_t pa0 = packbf(sacc[2 * j][0], sacc[2 * j][1]);
            uint32_t pa1 = packbf(sacc[2 * j][2], sacc[2 * j][3]);
            uint32_t pa2 = packbf(sacc[2 * j + 1][0], sacc[2 * j + 1][1]);
            uint32_t pa3 = packbf(sacc[2 * j + 1][2], sacc[2 * j + 1][3]);
#pragma unroll
            for (int nb = 0; nb < 2; nb++) {
                uint32_t b0, b1, b2, b3;
                uint32_t addr = smem_u32(&Vs[j * 16 + (lane & 15)][nb * 32 + (lane >> 4) * 8]);
                ldsm_x4_t(b0, b1, b2, b3, addr);
                mma_bf16(oacc[nb * 4 + 0], pa0, pa1, pa2, pa3, b0, b1);
                mma_bf16(oacc[nb * 4 + 1], pa0, pa1, pa2, pa3, b2, b3);
                addr = smem_u32(&Vs[j * 16 + (lane & 15)][nb * 32 + 16 + (lane >> 4) * 8]);
                ldsm_x4_t(b0, b1, b2, b3, addr);
                mma_bf16(oacc[nb * 4 + 2], pa0, pa1, pa2, pa3, b0, b1);
                mma_bf16(oacc[nb * 4 + 3], pa0, pa1, pa2, pa3, b2, b3);
            }
        }
    }

    // write O / l
#pragma unroll
    for (int half = 0; half < 2; half++) {
        float inv = 1.0f / l_run[half];
        int row = q0 + wq + (lane >> 2) + half * 8;
        float* dst = g_attn + (size_t)(b * SEQ + row) * DM + h * HD;
#pragma unroll
        for (int nj = 0; nj < 8; nj++) {
            int col = nj * 8 + 2 * (lane & 3);
            *(float2*)&dst[col] = make_float2(oacc[nj][half * 2 + 0] * inv,
                                              oacc[nj][half * 2 + 1] * inv);
        }
    }
}

// ---------------- layernorm (one block per token row) ----------------
__global__ void ln_kernel(const float* __restrict__ x, const float* __restrict__ gam,
                          const float* __restrict__ bet, float* __restrict__ y) {
    int row = blockIdx.x;
    int tid = threadIdx.x;  // 256
    __shared__ float sx[DM];
    __shared__ float red[256];
    const float* xr = x + (size_t)row * DM;
    float s = 0.f;
    for (int i = tid; i < DM; i += 256) { float v = xr[i]; sx[i] = v; s += v; }
    red[tid] = s; __syncthreads();
    for (int o = 128; o > 0; o >>= 1) { if (tid < o) red[tid] += red[tid + o]; __syncthreads(); }
    float m = red[0] * (1.0f / DM);
    __syncthreads();
    float s2 = 0.f;
    for (int i = tid; i < DM; i += 256) { float d = sx[i] - m; s2 += d * d; }
    red[tid] = s2; __syncthreads();
    for (int o = 128; o > 0; o >>= 1) { if (tid < o) red[tid] += red[tid + o]; __syncthreads(); }
    float var = red[0] * (1.0f / DM);
    float r = rsqrtf(var + 1e-5f);
    for (int i = tid; i < DM; i += 256)
        y[(size_t)row * DM + i] = (sx[i] - m) * r * gam[i] + bet[i];
}

// ---------------- router ----------------
__global__ void router_kernel(const float* __restrict__ Wr, const float* __restrict__ br) {
    int t = blockIdx.x, tid = threadIdx.x;  // 64 threads
    float acc[NEXP] = {};
    const float* xr = g_xn2 + (size_t)t * DM;
    for (int d = tid; d < DM; d += 64) {
        float xv = xr[d];
        const float* w = Wr + (size_t)d * NEXP;
#pragma unroll
        for (int e = 0; e < NEXP; e++) acc[e] += xv * w[e];
    }
    __shared__ float sh[64][NEXP + 1];
#pragma unroll
    for (int e = 0; e < NEXP; e++) sh[tid][e] = acc[e];
    __syncthreads();
    if (tid < NEXP) {
        float s = br[tid];
        for (int i = 0; i < 64; i++) s += sh[i][tid];
        sh[0][tid] = s;
    }
    __syncthreads();
    if (tid == 0) {
        float l[NEXP];
#pragma unroll
        for (int e = 0; e < NEXP; e++) l[e] = sh[0][e];
        int i1 = 0;
        for (int e = 1; e < NEXP; e++) if (l[e] > l[i1]) i1 = e;
        int i2 = (i1 == 0) ? 1 : 0;
        for (int e = 0; e < NEXP; e++) if (e != i1 && l[e] > l[i2]) i2 = e;
        float g1 = 1.0f / (1.0f + expf(l[i2] - l[i1]));
        float g2 = 1.0f - g1;
        g_top_e[2 * t] = i1; g_top_g[2 * t] = g1;
        g_top_e[2 * t + 1] = i2; g_top_g[2 * t + 1] = g2;
        atomicAdd(&g_cnt[i1], 1);
        atomicAdd(&g_cnt[i2], 1);
    }
}

__global__ void offsets_kernel() {
    if (threadIdx.x == 0) {
        int acc = 0;
#pragma unroll
        for (int e = 0; e < NEXP; e++) { g_off[e] = acc; acc += g_cnt[e]; }
    }
}

__global__ void scatter_kernel() {
    int i = blockIdx.x * 256 + threadIdx.x;
    if (i >= NSLOTS) return;
    int e = g_top_e[i];
    int p = atomicAdd(&g_fill[e], 1);
    int slot = g_off[e] + p;
    g_slot_tok[slot] = i >> 1;
    g_slot_gate[slot] = g_top_g[i];
}

// ---------------- launch ----------------
extern "C" void kernel_launch(void* const* d_in, const int* in_sizes, int n_in,
                              void* d_out, int out_size) {
    const float* x     = (const float*)d_in[0];
    const float* ln1_g = (const float*)d_in[1];
    const float* ln1_b = (const float*)d_in[2];
    const float* Wq    = (const float*)d_in[3];
    const float* Wk    = (const float*)d_in[4];
    const float* Wv    = (const float*)d_in[5];
    const float* Wo    = (const float*)d_in[6];
    const float* bo    = (const float*)d_in[7];
    const float* ln2_g = (const float*)d_in[8];
    const float* ln2_b = (const float*)d_in[9];
    const float* Wr    = (const float*)d_in[10];
    const float* br    = (const float*)d_in[11];
    const float* W1    = (const float*)d_in[12];
    const float* b1    = (const float*)d_in[13];
    const float* W2    = (const float*)d_in[14];
    const float* b2    = (const float*)d_in[15];
    float* out = (float*)d_out;

    float *xn1_p, *attn_p, *xn2_p;
    cudaGetSymbolAddress((void**)&xn1_p, g_xn1);
    cudaGetSymbolAddress((void**)&attn_p, g_attn);
    cudaGetSymbolAddress((void**)&xn2_p, g_xn2);

    zero_cnt_kernel<<<1, 32>>>();
    ln_kernel<<<TOKENS, 256>>>(x, ln1_g, ln1_b, xn1_p);

    // fused QKV: 18 x 16 = 288 CTAs, one launch
    bgemm<4><<<dim3(18, TOKENS / 128), 256>>>(nullptr, Wq, Wk, Wv, nullptr, DM, DM);

    // fused flash attention: replaces scores + softmax + av (and 96MB scratch)
    flash_attn_kernel<<<dim3(SEQ / 64, BH), 128>>>();

    // h = x + attn @ Wo + bo, written DIRECTLY into d_out
    bgemm<1><<<dim3(DM / 128, TOKENS / 128), 256>>>(attn_p, Wo, bo, x, out, DM, DM);

    ln_kernel<<<TOKENS, 256>>>(out, ln2_g, ln2_b, xn2_p);

    router_kernel<<<TOKENS, 64>>>(Wr, br);
    offsets_kernel<<<1, 32>>>();
    scatter_kernel<<<(NSLOTS + 255) / 256, 256>>>();

    bgemm<2><<<dim3(DFF / 128, TOKENS / 128, NEXP), 256>>>(nullptr, W1, b1, nullptr, nullptr, DFF, DM);
    bgemm<3><<<dim3(DM / 128, TOKENS / 128, NEXP), 256>>>(nullptr, W2, b2, nullptr, out, DM, DFF);
}

// round 9
// speedup vs baseline: 4.7452x; 1.3554x over previous
#include <cuda_runtime.h>
#include <cuda_bf16.h>
#include <stdint.h>
#include <stddef.h>
#include <math.h>

#define TOKENS 2048
#define DM 768
#define DFF 3072
#define NEXP 8
#define SEQ 1024
#define NH 12
#define BH 24
#define HD 64
#define NSLOTS (2 * TOKENS)

// ---------------- scratch (static device globals; no allocations) ----------------
__device__ unsigned short g_xn1b[TOKENS * DM];
__device__ float          g_xn2[TOKENS * DM];
__device__ unsigned short g_xn2b[TOKENS * DM];
__device__ unsigned short g_qb[TOKENS * DM];
__device__ unsigned short g_kb[TOKENS * DM];
__device__ unsigned short g_vb[TOKENS * DM];
__device__ unsigned short g_attnb[TOKENS * DM];
__device__ unsigned short g_hbuf[(size_t)NSLOTS * DFF];
// bf16 weights
__device__ unsigned short g_wqb[DM * DM];
__device__ unsigned short g_wkb[DM * DM];
__device__ unsigned short g_wvb[DM * DM];
__device__ unsigned short g_wob[DM * DM];
__device__ unsigned short g_w1b[(size_t)NEXP * DM * DFF];
__device__ unsigned short g_w2b[(size_t)NEXP * DFF * DM];
// routing
__device__ int   g_cnt[NEXP];
__device__ int   g_off[NEXP];
__device__ int   g_fill[NEXP];
__device__ int   g_top_e[NSLOTS];
__device__ float g_top_g[NSLOTS];
__device__ int   g_slot_tok[NSLOTS];
__device__ float g_slot_gate[NSLOTS];

// ---------------- helpers ----------------
__global__ void zero_cnt_kernel() {
    int t = threadIdx.x;
    if (t < NEXP) { g_cnt[t] = 0; g_fill[t] = 0; }
}

__device__ __forceinline__ uint32_t smem_u32(const void* p) {
    return (uint32_t)__cvta_generic_to_shared(p);
}
__device__ __forceinline__ uint32_t packbf(float x, float y) {
    __nv_bfloat162 h = __floats2bfloat162_rn(x, y);
    return *(uint32_t*)&h;
}
__device__ __forceinline__ void cp16(uint32_t saddr, const void* g) {
    asm volatile("cp.async.cg.shared.global [%0], [%1], 16;" :: "r"(saddr), "l"(g));
}
__device__ __forceinline__ void cp16z(uint32_t saddr, const void* g, int sz) {
    asm volatile("cp.async.cg.shared.global [%0], [%1], 16, %2;" :: "r"(saddr), "l"(g), "r"(sz));
}
#define CP_COMMIT() asm volatile("cp.async.commit_group;")
#define CP_WAIT(N)  asm volatile("cp.async.wait_group %0;" :: "n"(N))

__device__ __forceinline__ void ldsm_x4(uint32_t& r0, uint32_t& r1, uint32_t& r2, uint32_t& r3, uint32_t addr) {
    asm volatile("ldmatrix.sync.aligned.m8n8.x4.shared.b16 {%0,%1,%2,%3}, [%4];"
                 : "=r"(r0), "=r"(r1), "=r"(r2), "=r"(r3) : "r"(addr));
}
__device__ __forceinline__ void ldsm_x4_t(uint32_t& r0, uint32_t& r1, uint32_t& r2, uint32_t& r3, uint32_t addr) {
    asm volatile("ldmatrix.sync.aligned.m8n8.x4.trans.shared.b16 {%0,%1,%2,%3}, [%4];"
                 : "=r"(r0), "=r"(r1), "=r"(r2), "=r"(r3) : "r"(addr));
}
__device__ __forceinline__ void mma_bf16(float* c, uint32_t a0, uint32_t a1, uint32_t a2, uint32_t a3,
                                         uint32_t b0, uint32_t b1) {
    asm volatile("mma.sync.aligned.m16n8k16.row.col.f32.bf16.bf16.f32 "
                 "{%0,%1,%2,%3},{%4,%5,%6,%7},{%8,%9},{%0,%1,%2,%3};"
                 : "+f"(c[0]), "+f"(c[1]), "+f"(c[2]), "+f"(c[3])
                 : "r"(a0), "r"(a1), "r"(a2), "r"(a3), "r"(b0), "r"(b1));
}
__device__ __forceinline__ float gelu_exact(float x) {
    return 0.5f * x * (1.0f + erff(x * 0.70710678118654752f));
}

// ---------------- weight conversion (fp32 -> bf16) ----------------
__global__ void cvt_qkvo_kernel(const float* __restrict__ Wq, const float* __restrict__ Wk,
                                const float* __restrict__ Wv, const float* __restrict__ Wo) {
    int seg = blockIdx.y;
    const float* src = (seg == 0) ? Wq : (seg == 1) ? Wk : (seg == 2) ? Wv : Wo;
    unsigned short* dst = (seg == 0) ? g_wqb : (seg == 1) ? g_wkb : (seg == 2) ? g_wvb : g_wob;
    int i = (blockIdx.x * 256 + threadIdx.x) * 4;
    float4 v = *(const float4*)(src + i);
    *(uint2*)(dst + i) = make_uint2(packbf(v.x, v.y), packbf(v.z, v.w));
}
__global__ void cvt_big_kernel(const float* __restrict__ src, unsigned short* __restrict__ dst) {
    size_t i = ((size_t)blockIdx.x * 256 + threadIdx.x) * 8;
    float4 a = *(const float4*)(src + i);
    float4 b = *(const float4*)(src + i + 4);
    *(uint4*)(dst + i) = make_uint4(packbf(a.x, a.y), packbf(a.z, a.w),
                                    packbf(b.x, b.y), packbf(b.z, b.w));
}

// ---------------- bf16 GEMM, cp.async 3-stage pipeline ----------------
// MODE 1: out = attnb @ Wo + bo + x          (fp32 out)
// MODE 2: hbuf = gelu(gather(xn2b) @ W1[e] + b1[e])
// MODE 3: out[tok] += gate * (hbuf @ W2[e] + b2[e])   (atomic)
// MODE 4: {qb,kb,vb} = xn1b @ {Wq,Wk,Wv}     (bf16 out, seg by blockIdx.x/6)
#define AS_EL(S, R, Cc) sm[(S) * 5120 + (R) * 40 + (Cc)]
#define BS_EL(S, R, Cc) sm[15360 + (S) * 4352 + (R) * 136 + (Cc)]

template<int MODE>
__global__ __launch_bounds__(256)
void bgemm(const float* __restrict__ bias, const float* __restrict__ res,
           float* __restrict__ C, int N, int Kdim) {
    extern __shared__ unsigned short sm[];
    int e = (MODE == 2 || MODE == 3) ? blockIdx.z : 0;
    int cnt = 0, off = 0;
    if (MODE == 2 || MODE == 3) {
        cnt = g_cnt[e];
        off = g_off[e];
        if ((int)blockIdx.y * 128 >= cnt) return;
    }
    const unsigned short* Bp;
    unsigned short* outp16 = nullptr;
    int m00 = blockIdx.y * 128;
    int col0 = blockIdx.x * 128;
    if (MODE == 1)      Bp = g_wob;
    else if (MODE == 2) Bp = g_w1b + (size_t)e * DM * DFF;
    else if (MODE == 3) Bp = g_w2b + (size_t)e * DFF * DM;
    else {  // MODE 4
        int seg = blockIdx.x / 6;
        Bp = (seg == 0) ? g_wqb : (seg == 1) ? g_wkb : g_wvb;
        outp16 = (seg == 0) ? g_qb : (seg == 1) ? g_kb : g_vb;
        col0 = (blockIdx.x % 6) * 128;
    }

    int tid = threadIdx.x, lane = tid & 31, warp = tid >> 5;
    int wm = (warp & 1) * 64, wn = (warp >> 1) * 32;
    int ar = tid >> 1, akc = (tid & 1) * 16;
    int bkr = tid >> 3, bc = (tid & 7) * 16;

    const unsigned short* abase;
    int azf = 16;
    if (MODE == 4)      abase = g_xn1b + (size_t)(m00 + ar) * DM;
    else if (MODE == 1) abase = g_attnb + (size_t)(m00 + ar) * DM;
    else if (MODE == 2) {
        int rc = m00 + ar;
        if (rc < cnt) abase = g_xn2b + (size_t)g_slot_tok[off + rc] * DM;
        else { abase = g_xn2b; azf = 0; }
    } else {
        int rc = m00 + ar;
        if (rc < cnt) abase = g_hbuf + (size_t)(off + rc) * DFF;
        else { abase = g_hbuf; azf = 0; }
    }
    const unsigned short* bbase = Bp + (size_t)bkr * N + col0 + bc;

#define ISSUE_TILE(S, K0)                                                   \
    do {                                                                    \
        uint32_t da = smem_u32(&AS_EL(S, ar, akc));                         \
        cp16z(da, abase + (K0) + akc, azf);                                 \
        cp16z(da + 16, abase + (K0) + akc + 8, azf);                        \
        uint32_t db = smem_u32(&BS_EL(S, bkr, bc));                         \
        const unsigned short* bs_ = bbase + (size_t)(K0) * N;               \
        cp16(db, bs_);                                                      \
        cp16(db + 16, bs_ + 8);                                             \
    } while (0)

    int nIter = Kdim >> 5;
    ISSUE_TILE(0, 0); CP_COMMIT();
    ISSUE_TILE(1, 32); CP_COMMIT();

    float acc[4][4][4] = {};

    for (int it = 0; it < nIter; it++) {
        int stage = it % 3;
        CP_WAIT(1);
        __syncthreads();
        {
            int nt = it + 2;
            if (nt < nIter) ISSUE_TILE(nt % 3, nt << 5);
            CP_COMMIT();
        }
#pragma unroll
        for (int ks = 0; ks < 2; ks++) {
            int kk = ks * 16;
            uint32_t a[4][4];
#pragma unroll
            for (int mi = 0; mi < 4; mi++) {
                uint32_t addr = smem_u32(&AS_EL(stage, wm + mi * 16 + (lane & 15), kk + (lane >> 4) * 8));
                ldsm_x4(a[mi][0], a[mi][1], a[mi][2], a[mi][3], addr);
            }
            uint32_t b[4][2];
#pragma unroll
            for (int nb = 0; nb < 2; nb++) {
                uint32_t addr = smem_u32(&BS_EL(stage, kk + (lane & 15), wn + nb * 16 + (lane >> 4) * 8));
                ldsm_x4_t(b[nb * 2][0], b[nb * 2][1], b[nb * 2 + 1][0], b[nb * 2 + 1][1], addr);
            }
#pragma unroll
            for (int mi = 0; mi < 4; mi++)
#pragma unroll
                for (int nj = 0; nj < 4; nj++)
                    mma_bf16(acc[mi][nj], a[mi][0], a[mi][1], a[mi][2], a[mi][3],
                             b[nj][0], b[nj][1]);
        }
        __syncthreads();
    }
#undef ISSUE_TILE

    int g = lane >> 2, t4 = lane & 3;
#pragma unroll
    for (int mi = 0; mi < 4; mi++) {
#pragma unroll
        for (int h2 = 0; h2 < 2; h2++) {
            int rloc = wm + mi * 16 + g + h2 * 8;
            if (MODE == 2 || MODE == 3) {
                int rc = m00 + rloc;
                if (rc >= cnt) continue;
                int slot = off + rc;
                if (MODE == 2) {
                    size_t base = (size_t)slot * DFF;
#pragma unroll
                    for (int nj = 0; nj < 4; nj++) {
                        int col = col0 + wn + nj * 8 + 2 * t4;
                        float v0 = gelu_exact(acc[mi][nj][h2 * 2 + 0] + bias[(size_t)e * DFF + col]);
                        float v1 = gelu_exact(acc[mi][nj][h2 * 2 + 1] + bias[(size_t)e * DFF + col + 1]);
                        *(uint32_t*)&g_hbuf[base + col] = packbf(v0, v1);
                    }
                } else {
                    int tok = g_slot_tok[slot];
                    float gt = g_slot_gate[slot];
#pragma unroll
                    for (int nj = 0; nj < 4; nj++) {
                        int col = col0 + wn + nj * 8 + 2 * t4;
                        float v0 = (acc[mi][nj][h2 * 2 + 0] + bias[(size_t)e * DM + col]) * gt;
                        float v1 = (acc[mi][nj][h2 * 2 + 1] + bias[(size_t)e * DM + col + 1]) * gt;
                        atomicAdd(&C[(size_t)tok * DM + col], v0);
                        atomicAdd(&C[(size_t)tok * DM + col + 1], v1);
                    }
                }
            } else if (MODE == 1) {
                int row = m00 + rloc;
#pragma unroll
                for (int nj = 0; nj < 4; nj++) {
                    int col = col0 + wn + nj * 8 + 2 * t4;
                    float v0 = acc[mi][nj][h2 * 2 + 0] + bias[col] + res[(size_t)row * N + col];
                    float v1 = acc[mi][nj][h2 * 2 + 1] + bias[col + 1] + res[(size_t)row * N + col + 1];
                    *(float2*)&C[(size_t)row * N + col] = make_float2(v0, v1);
                }
            } else {  // MODE 4: bf16 out
                int row = m00 + rloc;
#pragma unroll
                for (int nj = 0; nj < 4; nj++) {
                    int col = col0 + wn + nj * 8 + 2 * t4;
                    *(uint32_t*)&outp16[(size_t)row * DM + col] =
                        packbf(acc[mi][nj][h2 * 2 + 0], acc[mi][nj][h2 * 2 + 1]);
                }
            }
        }
    }
}

// ---------------- fused flash attention (bf16 in/out, cp.async double-buffer) ----
__global__ __launch_bounds__(128)
void flash_attn_kernel() {
    int bh = blockIdx.y; int b = bh / NH, h = bh % NH;
    int qt = (int)(gridDim.x - 1) - (int)blockIdx.x;  // heavy tiles first
    int q0 = qt * 64;
    int tid = threadIdx.x, lane = tid & 31, warp = tid >> 5;
    int wq = warp * 16;

    __shared__ unsigned short Qs[64][72];
    __shared__ unsigned short Ks[2][64][72];
    __shared__ unsigned short Vs[2][64][72];

    int lr = tid >> 1, lc = (tid & 1) * 32;

#define FA_ISSUE(BUF, K0)                                                          \
    do {                                                                           \
        const unsigned short* kp = g_kb + (size_t)(b * SEQ + (K0) + lr) * DM + h * HD + lc; \
        const unsigned short* vp = g_vb + (size_t)(b * SEQ + (K0) + lr) * DM + h * HD + lc; \
        uint32_t ka = smem_u32(&Ks[BUF][lr][lc]);                                  \
        uint32_t va = smem_u32(&Vs[BUF][lr][lc]);                                  \
        cp16(ka, kp); cp16(ka + 16, kp + 8); cp16(ka + 32, kp + 16); cp16(ka + 48, kp + 24); \
        cp16(va, vp); cp16(va + 16, vp + 8); cp16(va + 32, vp + 16); cp16(va + 48, vp + 24); \
    } while (0)

    // start fetching kv tile 0 immediately
    FA_ISSUE(0, 0);
    CP_COMMIT();

    // load Q tile (bf16 copy)
    {
        const unsigned short* qp = g_qb + (size_t)(b * SEQ + q0 + lr) * DM + h * HD + lc;
        *(uint4*)&Qs[lr][lc]      = *(const uint4*)(qp);
        *(uint4*)&Qs[lr][lc + 8]  = *(const uint4*)(qp + 8);
        *(uint4*)&Qs[lr][lc + 16] = *(const uint4*)(qp + 16);
        *(uint4*)&Qs[lr][lc + 24] = *(const uint4*)(qp + 24);
    }
    __syncthreads();

    uint32_t qa[4][4];
#pragma unroll
    for (int kc = 0; kc < 4; kc++) {
        uint32_t addr = smem_u32(&Qs[wq + (lane & 15)][kc * 16 + (lane >> 4) * 8]);
        ldsm_x4(qa[kc][0], qa[kc][1], qa[kc][2], qa[kc][3], addr);
    }

    float m_run[2] = {-1e30f, -1e30f};
    float l_run[2] = {0.f, 0.f};
    float oacc[8][4] = {};

    for (int kt = 0; kt <= qt; kt++) {
        int k0 = kt * 64;
        int buf = kt & 1;
        CP_WAIT(0);
        __syncthreads();
        if (kt < qt) { FA_ISSUE(buf ^ 1, k0 + 64); CP_COMMIT(); }

        // S = Q K^T
        float sacc[8][4] = {};
#pragma unroll
        for (int kc = 0; kc < 4; kc++) {
#pragma unroll
            for (int nb = 0; nb < 4; nb++) {
                uint32_t r0, r1, r2, r3;
                uint32_t addr = smem_u32(&Ks[buf][nb * 16 + (lane & 7) + ((lane >> 3) & 1) * 8]
                                            [kc * 16 + (lane >> 4) * 8]);
                ldsm_x4(r0, r1, r2, r3, addr);
                mma_bf16(sacc[nb * 2],     qa[kc][0], qa[kc][1], qa[kc][2], qa[kc][3], r0, r2);
                mma_bf16(sacc[nb * 2 + 1], qa[kc][0], qa[kc][1], qa[kc][2], qa[kc][3], r1, r3);
            }
        }

        // online softmax
        bool diag = (kt == qt);
#pragma unroll
        for (int half = 0; half < 2; half++) {
            int qrow = q0 + wq + (lane >> 2) + half * 8;
            float vals[16];
#pragma unroll
            for (int nj = 0; nj < 8; nj++) {
                int colg = k0 + nj * 8 + 2 * (lane & 3);
                float v0 = sacc[nj][half * 2 + 0] * 0.125f;
                float v1 = sacc[nj][half * 2 + 1] * 0.125f;
                if (diag) {
                    if (colg > qrow) v0 = -1e30f;
                    if (colg + 1 > qrow) v1 = -1e30f;
                }
                vals[nj * 2] = v0;
                vals[nj * 2 + 1] = v1;
            }
            float tmx = vals[0];
#pragma unroll
            for (int i = 1; i < 16; i++) tmx = fmaxf(tmx, vals[i]);
            tmx = fmaxf(tmx, __shfl_xor_sync(0xffffffffu, tmx, 1));
            tmx = fmaxf(tmx, __shfl_xor_sync(0xffffffffu, tmx, 2));
            float mnew = fmaxf(m_run[half], tmx);
            float corr = __expf(m_run[half] - mnew);
            float rsum = 0.f;
#pragma unroll
            for (int i = 0; i < 16; i++) {
                float p = __expf(vals[i] - mnew);
                vals[i] = p;
                rsum += p;
            }
            rsum += __shfl_xor_sync(0xffffffffu, rsum, 1);
            rsum += __shfl_xor_sync(0xffffffffu, rsum, 2);
            l_run[half] = l_run[half] * corr + rsum;
            m_run[half] = mnew;
#pragma unroll
            for (int nj = 0; nj < 8; nj++) {
                oacc[nj][half * 2 + 0] *= corr;
                oacc[nj][half * 2 + 1] *= corr;
                sacc[nj][half * 2 + 0] = vals[nj * 2];
                sacc[nj][half * 2 + 1] = vals[nj * 2 + 1];
            }
        }

        // O += P @ V
#pragma unroll
        for (int j = 0; j < 4; j++) {
            uint32_t pa0 = packbf(sacc[2 * j][0], sacc[2 * j][1]);
            uint32_t pa1 = packbf(sacc[2 * j][2], sacc[2 * j][3]);
            uint32_t pa2 = packbf(sacc[2 * j + 1][0], sacc[2 * j + 1][1]);
            uint32_t pa3 = packbf(sacc[2 * j + 1][2], sacc[2 * j + 1][3]);
#pragma unroll
            for (int nb = 0; nb < 2; nb++) {
                uint32_t b0, b1, b2, b3;
                uint32_t addr = smem_u32(&Vs[buf][j * 16 + (lane & 15)][nb * 32 + (lane >> 4) * 8]);
                ldsm_x4_t(b0, b1, b2, b3, addr);
                mma_bf16(oacc[nb * 4 + 0], pa0, pa1, pa2, pa3, b0, b1);
                mma_bf16(oacc[nb * 4 + 1], pa0, pa1, pa2, pa3, b2, b3);
                addr = smem_u32(&Vs[buf][j * 16 + (lane & 15)][nb * 32 + 16 + (lane >> 4) * 8]);
                ldsm_x4_t(b0, b1, b2, b3, addr);
                mma_bf16(oacc[nb * 4 + 2], pa0, pa1, pa2, pa3, b0, b1);
                mma_bf16(oacc[nb * 4 + 3], pa0, pa1, pa2, pa3, b2, b3);
            }
        }
    }
#undef FA_ISSUE

    // write O (bf16)
#pragma unroll
    for (int half = 0; half < 2; half++) {
        float inv = 1.0f / l_run[half];
        int row = q0 + wq + (lane >> 2) + half * 8;
        unsigned short* dst = g_attnb + (size_t)(b * SEQ + row) * DM + h * HD;
#pragma unroll
        for (int nj = 0; nj < 8; nj++) {
            int col = nj * 8 + 2 * (lane & 3);
            *(uint32_t*)&dst[col] = packbf(oacc[nj][half * 2 + 0] * inv,
                                           oacc[nj][half * 2 + 1] * inv);
        }
    }
}

// ---------------- layernorm: writes bf16 always, fp32 optionally ----------------
__global__ void ln_kernel(const float* __restrict__ x, const float* __restrict__ gam,
                          const float* __restrict__ bet, float* __restrict__ yf,
                          unsigned short* __restrict__ yb) {
    int row = blockIdx.x;
    int tid = threadIdx.x;  // 256
    __shared__ float sx[DM];
    __shared__ float red[256];
    const float* xr = x + (size_t)row * DM;
    float s = 0.f;
    for (int i = tid; i < DM; i += 256) { float v = xr[i]; sx[i] = v; s += v; }
    red[tid] = s; __syncthreads();
    for (int o = 128; o > 0; o >>= 1) { if (tid < o) red[tid] += red[tid + o]; __syncthreads(); }
    float m = red[0] * (1.0f / DM);
    __syncthreads();
    float s2 = 0.f;
    for (int i = tid; i < DM; i += 256) { float d = sx[i] - m; s2 += d * d; }
    red[tid] = s2; __syncthreads();
    for (int o = 128; o > 0; o >>= 1) { if (tid < o) red[tid] += red[tid + o]; __syncthreads(); }
    float var = red[0] * (1.0f / DM);
    float r = rsqrtf(var + 1e-5f);
    for (int i = tid; i < DM; i += 256) {
        float v = (sx[i] - m) * r * gam[i] + bet[i];
        if (yf) yf[(size_t)row * DM + i] = v;
        yb[(size_t)row * DM + i] = __bfloat16_as_ushort(__float2bfloat16(v));
    }
}

// ---------------- router ----------------
__global__ void router_kernel(const float* __restrict__ Wr, const float* __restrict__ br) {
    int t = blockIdx.x, tid = threadIdx.x;  // 64 threads
    float acc[NEXP] = {};
    const float* xr = g_xn2 + (size_t)t * DM;
    for (int d = tid; d < DM; d += 64) {
        float xv = xr[d];
        const float* w = Wr + (size_t)d * NEXP;
#pragma unroll
        for (int e = 0; e < NEXP; e++) acc[e] += xv * w[e];
    }
    __shared__ float sh[64][NEXP + 1];
#pragma unroll
    for (int e = 0; e < NEXP; e++) sh[tid][e] = acc[e];
    __syncthreads();
    if (tid < NEXP) {
        float s = br[tid];
        for (int i = 0; i < 64; i++) s += sh[i][tid];
        sh[0][tid] = s;
    }
    __syncthreads();
    if (tid == 0) {
        float l[NEXP];
#pragma unroll
        for (int e = 0; e < NEXP; e++) l[e] = sh[0][e];
        int i1 = 0;
        for (int e = 1; e < NEXP; e++) if (l[e] > l[i1]) i1 = e;
        int i2 = (i1 == 0) ? 1 : 0;
        for (int e = 0; e < NEXP; e++) if (e != i1 && l[e] > l[i2]) i2 = e;
        float g1 = 1.0f / (1.0f + expf(l[i2] - l[i1]));
        float g2 = 1.0f - g1;
        g_top_e[2 * t] = i1; g_top_g[2 * t] = g1;
        g_top_e[2 * t + 1] = i2; g_top_g[2 * t + 1] = g2;
        atomicAdd(&g_cnt[i1], 1);
        atomicAdd(&g_cnt[i2], 1);
    }
}

__global__ void offsets_kernel() {
    if (threadIdx.x == 0) {
        int acc = 0;
#pragma unroll
        for (int e = 0; e < NEXP; e++) { g_off[e] = acc; acc += g_cnt[e]; }
    }
}

__global__ void scatter_kernel() {
    int i = blockIdx.x * 256 + threadIdx.x;
    if (i >= NSLOTS) return;
    int e = g_top_e[i];
    int p = atomicAdd(&g_fill[e], 1);
    int slot = g_off[e] + p;
    g_slot_tok[slot] = i >> 1;
    g_slot_gate[slot] = g_top_g[i];
}

// ---------------- launch ----------------
extern "C" void kernel_launch(void* const* d_in, const int* in_sizes, int n_in,
                              void* d_out, int out_size) {
    const float* x     = (const float*)d_in[0];
    const float* ln1_g = (const float*)d_in[1];
    const float* ln1_b = (const float*)d_in[2];
    const float* Wq    = (const float*)d_in[3];
    const float* Wk    = (const float*)d_in[4];
    const float* Wv    = (const float*)d_in[5];
    const float* Wo    = (const float*)d_in[6];
    const float* bo    = (const float*)d_in[7];
    const float* ln2_g = (const float*)d_in[8];
    const float* ln2_b = (const float*)d_in[9];
    const float* Wr    = (const float*)d_in[10];
    const float* br    = (const float*)d_in[11];
    const float* W1    = (const float*)d_in[12];
    const float* b1    = (const float*)d_in[13];
    const float* W2    = (const float*)d_in[14];
    const float* b2    = (const float*)d_in[15];
    float* out = (float*)d_out;

    float* xn2_p;
    unsigned short *xn1b_p, *xn2b_p, *w1b_p, *w2b_p;
    cudaGetSymbolAddress((void**)&xn2_p, g_xn2);
    cudaGetSymbolAddress((void**)&xn1b_p, g_xn1b);
    cudaGetSymbolAddress((void**)&xn2b_p, g_xn2b);
    cudaGetSymbolAddress((void**)&w1b_p, g_w1b);
    cudaGetSymbolAddress((void**)&w2b_p, g_w2b);

    const int BG_SMEM = (3 * 128 * 40 + 3 * 32 * 136) * 2;  // 56832 B
    cudaFuncSetAttribute(bgemm<1>, cudaFuncAttributeMaxDynamicSharedMemorySize, BG_SMEM);
    cudaFuncSetAttribute(bgemm<2>, cudaFuncAttributeMaxDynamicSharedMemorySize, BG_SMEM);
    cudaFuncSetAttribute(bgemm<3>, cudaFuncAttributeMaxDynamicSharedMemorySize, BG_SMEM);
    cudaFuncSetAttribute(bgemm<4>, cudaFuncAttributeMaxDynamicSharedMemorySize, BG_SMEM);

    zero_cnt_kernel<<<1, 32>>>();
    // weight conversions
    cvt_qkvo_kernel<<<dim3(576, 4), 256>>>(Wq, Wk, Wv, Wo);
    cvt_big_kernel<<<9216, 256>>>(W1, w1b_p);
    cvt_big_kernel<<<9216, 256>>>(W2, w2b_p);

    ln_kernel<<<TOKENS, 256>>>(x, ln1_g, ln1_b, nullptr, xn1b_p);

    // fused QKV (bf16 out)
    bgemm<4><<<dim3(18, TOKENS / 128), 256, BG_SMEM>>>(nullptr, nullptr, nullptr, DM, DM);

    flash_attn_kernel<<<dim3(SEQ / 64, BH), 128>>>();

    // h = x + attn @ Wo + bo -> d_out (fp32)
    bgemm<1><<<dim3(DM / 128, TOKENS / 128), 256, BG_SMEM>>>(bo, x, out, DM, DM);

    ln_kernel<<<TOKENS, 256>>>(out, ln2_g, ln2_b, xn2_p, xn2b_p);

    router_kernel<<<TOKENS, 64>>>(Wr, br);
    offsets_kernel<<<1, 32>>>();
    scatter_kernel<<<(NSLOTS + 255) / 256, 256>>>();

    bgemm<2><<<dim3(DFF / 128, TOKENS / 128, NEXP), 256, BG_SMEM>>>(b1, nullptr, nullptr, DFF, DM);
    bgemm<3><<<dim3(DM / 128, TOKENS / 128, NEXP), 256, BG_SMEM>>>(b2, nullptr, out, DM, DFF);
}

// round 11
// speedup vs baseline: 4.7651x; 1.0042x over previous
#include <cuda_runtime.h>
#include <cuda_bf16.h>
#include <cuda_fp16.h>
#include <stdint.h>
#include <stddef.h>
#include <math.h>

#define TOKENS 2048
#define DM 768
#define DFF 3072
#define NEXP 8
#define SEQ 1024
#define NH 12
#define BH 24
#define HD 64
#define NSLOTS (2 * TOKENS)

// ---------------- scratch (static device globals; no allocations) ----------------
__device__ __align__(16) unsigned short g_xn1b[TOKENS * DM];
__device__ __align__(16) float          g_xn2[TOKENS * DM];
__device__ __align__(16) unsigned short g_xn2b[TOKENS * DM];
__device__ __align__(16) unsigned short g_qb[TOKENS * DM];
__device__ __align__(16) unsigned short g_kb[TOKENS * DM];
__device__ __align__(16) unsigned short g_vb[TOKENS * DM];
__device__ __align__(16) unsigned short g_attnb[TOKENS * DM];
__device__ __align__(16) unsigned short g_hbuf[(size_t)NSLOTS * DFF];
// bf16 weights
__device__ __align__(16) unsigned short g_wqb[DM * DM];
__device__ __align__(16) unsigned short g_wkb[DM * DM];
__device__ __align__(16) unsigned short g_wvb[DM * DM];
__device__ __align__(16) unsigned short g_wob[DM * DM];
__device__ __align__(16) unsigned short g_w1b[(size_t)NEXP * DM * DFF];
__device__ __align__(16) unsigned short g_w2b[(size_t)NEXP * DFF * DM];
// routing
__device__ int   g_cnt[NEXP];
__device__ int   g_off[NEXP];
__device__ int   g_fill[NEXP];
__device__ int   g_top_e[NSLOTS];
__device__ float g_top_g[NSLOTS];
__device__ int   g_slot_tok[NSLOTS];
__device__ float g_slot_gate[NSLOTS];

// ---------------- helpers ----------------
__global__ void zero_cnt_kernel() {
    int t = threadIdx.x;
    if (t < NEXP) { g_cnt[t] = 0; g_fill[t] = 0; }
}

__device__ __forceinline__ uint32_t smem_u32(const void* p) {
    return (uint32_t)__cvta_generic_to_shared(p);
}
__device__ __forceinline__ uint32_t packbf(float x, float y) {
    __nv_bfloat162 h = __floats2bfloat162_rn(x, y);
    return *(uint32_t*)&h;
}
__device__ __forceinline__ void cp16(uint32_t saddr, const void* g) {
    asm volatile("cp.async.cg.shared.global [%0], [%1], 16;" :: "r"(saddr), "l"(g));
}
__device__ __forceinline__ void cp16z(uint32_t saddr, const void* g, int sz) {
    asm volatile("cp.async.cg.shared.global [%0], [%1], 16, %2;" :: "r"(saddr), "l"(g), "r"(sz));
}
#define CP_COMMIT() asm volatile("cp.async.commit_group;")
#define CP_WAIT(N)  asm volatile("cp.async.wait_group %0;" :: "n"(N))

__device__ __forceinline__ void ldsm_x4(uint32_t& r0, uint32_t& r1, uint32_t& r2, uint32_t& r3, uint32_t addr) {
    asm volatile("ldmatrix.sync.aligned.m8n8.x4.shared.b16 {%0,%1,%2,%3}, [%4];"
                 : "=r"(r0), "=r"(r1), "=r"(r2), "=r"(r3) : "r"(addr));
}
__device__ __forceinline__ void ldsm_x4_t(uint32_t& r0, uint32_t& r1, uint32_t& r2, uint32_t& r3, uint32_t addr) {
    asm volatile("ldmatrix.sync.aligned.m8n8.x4.trans.shared.b16 {%0,%1,%2,%3}, [%4];"
                 : "=r"(r0), "=r"(r1), "=r"(r2), "=r"(r3) : "r"(addr));
}
__device__ __forceinline__ void mma_bf16(float* c, uint32_t a0, uint32_t a1, uint32_t a2, uint32_t a3,
                                         uint32_t b0, uint32_t b1) {
    asm volatile("mma.sync.aligned.m16n8k16.row.col.f32.bf16.bf16.f32 "
                 "{%0,%1,%2,%3},{%4,%5,%6,%7},{%8,%9},{%0,%1,%2,%3};"
                 : "+f"(c[0]), "+f"(c[1]), "+f"(c[2]), "+f"(c[3])
                 : "r"(a0), "r"(a1), "r"(a2), "r"(a3), "r"(b0), "r"(b1));
}
__device__ __forceinline__ uint32_t ex2_f16x2(uint32_t a) {
    uint32_t r;
    asm volatile("ex2.approx.f16x2 %0, %1;" : "=r"(r) : "r"(a));
    return r;
}
__device__ __forceinline__ float gelu_exact(float x) {
    return 0.5f * x * (1.0f + erff(x * 0.70710678118654752f));
}

// ---------------- weight conversion (fp32 -> bf16) ----------------
__global__ void cvt_qkvo_kernel(const float* __restrict__ Wq, const float* __restrict__ Wk,
                                const float* __restrict__ Wv, const float* __restrict__ Wo) {
    int seg = blockIdx.y;
    const float* src = (seg == 0) ? Wq : (seg == 1) ? Wk : (seg == 2) ? Wv : Wo;
    unsigned short* dst = (seg == 0) ? g_wqb : (seg == 1) ? g_wkb : (seg == 2) ? g_wvb : g_wob;
    int i = (blockIdx.x * 256 + threadIdx.x) * 4;
    float4 v = *(const float4*)(src + i);
    *(uint2*)(dst + i) = make_uint2(packbf(v.x, v.y), packbf(v.z, v.w));
}
__global__ void cvt_big_kernel(const float* __restrict__ src, unsigned short* __restrict__ dst) {
    size_t i = ((size_t)blockIdx.x * 256 + threadIdx.x) * 8;
    float4 a = *(const float4*)(src + i);
    float4 b = *(const float4*)(src + i + 4);
    *(uint4*)(dst + i) = make_uint4(packbf(a.x, a.y), packbf(a.z, a.w),
                                    packbf(b.x, b.y), packbf(b.z, b.w));
}

// ---------------- bf16 GEMM, cp.async 4-stage pipeline ----------------
// MODE 1: out = attnb @ Wo + bo + x          (fp32 out)
// MODE 2: hbuf = gelu(gather(xn2b) @ W1[e] + b1[e])
// MODE 3: out[tok] += gate * (hbuf @ W2[e] + b2[e])   (atomic)
// MODE 4: {qb,kb,vb} = xn1b @ {Wq,Wk,Wv}     (bf16 out, seg by blockIdx.x/6)
#define AS_EL(S, R, Cc) sm[(S) * 5120 + (R) * 40 + (Cc)]
#define BS_EL(S, R, Cc) sm[20480 + (S) * 4352 + (R) * 136 + (Cc)]

template<int MODE>
__global__ __launch_bounds__(256)
void bgemm(const float* __restrict__ bias, const float* __restrict__ res,
           float* __restrict__ C, int N, int Kdim) {
    extern __shared__ unsigned short sm[];
    int e = (MODE == 2 || MODE == 3) ? blockIdx.z : 0;
    int cnt = 0, off = 0;
    if (MODE == 2 || MODE == 3) {
        cnt = g_cnt[e];
        off = g_off[e];
        if ((int)blockIdx.y * 128 >= cnt) return;
    }
    const unsigned short* Bp;
    unsigned short* outp16 = nullptr;
    int m00 = blockIdx.y * 128;
    int col0 = blockIdx.x * 128;
    if (MODE == 1)      Bp = g_wob;
    else if (MODE == 2) Bp = g_w1b + (size_t)e * DM * DFF;
    else if (MODE == 3) Bp = g_w2b + (size_t)e * DFF * DM;
    else {  // MODE 4
        int seg = blockIdx.x / 6;
        Bp = (seg == 0) ? g_wqb : (seg == 1) ? g_wkb : g_wvb;
        outp16 = (seg == 0) ? g_qb : (seg == 1) ? g_kb : g_vb;
        col0 = (blockIdx.x % 6) * 128;
    }

    int tid = threadIdx.x, lane = tid & 31, warp = tid >> 5;
    int wm = (warp & 1) * 64, wn = (warp >> 1) * 32;
    int ar = tid >> 1, akc = (tid & 1) * 16;
    int bkr = tid >> 3, bc = (tid & 7) * 16;

    const unsigned short* abase;
    int azf = 16;
    if (MODE == 4)      abase = g_xn1b + (size_t)(m00 + ar) * DM;
    else if (MODE == 1) abase = g_attnb + (size_t)(m00 + ar) * DM;
    else if (MODE == 2) {
        int rc = m00 + ar;
        if (rc < cnt) abase = g_xn2b + (size_t)g_slot_tok[off + rc] * DM;
        else { abase = g_xn2b; azf = 0; }
    } else {
        int rc = m00 + ar;
        if (rc < cnt) abase = g_hbuf + (size_t)(off + rc) * DFF;
        else { abase = g_hbuf; azf = 0; }
    }
    const unsigned short* bbase = Bp + (size_t)bkr * N + col0 + bc;

#define ISSUE_TILE(S, K0)                                                   \
    do {                                                                    \
        uint32_t da = smem_u32(&AS_EL(S, ar, akc));                         \
        cp16z(da, abase + (K0) + akc, azf);                                 \
        cp16z(da + 16, abase + (K0) + akc + 8, azf);                        \
        uint32_t db = smem_u32(&BS_EL(S, bkr, bc));                         \
        const unsigned short* bs_ = bbase + (size_t)(K0) * N;               \
        cp16(db, bs_);                                                      \
        cp16(db + 16, bs_ + 8);                                             \
    } while (0)

    int nIter = Kdim >> 5;
    ISSUE_TILE(0, 0);  CP_COMMIT();
    ISSUE_TILE(1, 32); CP_COMMIT();
    ISSUE_TILE(2, 64); CP_COMMIT();

    float acc[4][4][4] = {};

    for (int it = 0; it < nIter; it++) {
        int stage = it & 3;
        CP_WAIT(2);
        __syncthreads();
        {
            int nt = it + 3;
            if (nt < nIter) ISSUE_TILE(nt & 3, nt << 5);
            CP_COMMIT();
        }
#pragma unroll
        for (int ks = 0; ks < 2; ks++) {
            int kk = ks * 16;
            uint32_t a[4][4];
#pragma unroll
            for (int mi = 0; mi < 4; mi++) {
                uint32_t addr = smem_u32(&AS_EL(stage, wm + mi * 16 + (lane & 15), kk + (lane >> 4) * 8));
                ldsm_x4(a[mi][0], a[mi][1], a[mi][2], a[mi][3], addr);
            }
            uint32_t b[4][2];
#pragma unroll
            for (int nb = 0; nb < 2; nb++) {
                uint32_t addr = smem_u32(&BS_EL(stage, kk + (lane & 15), wn + nb * 16 + (lane >> 4) * 8));
                ldsm_x4_t(b[nb * 2][0], b[nb * 2][1], b[nb * 2 + 1][0], b[nb * 2 + 1][1], addr);
            }
#pragma unroll
            for (int mi = 0; mi < 4; mi++)
#pragma unroll
                for (int nj = 0; nj < 4; nj++)
                    mma_bf16(acc[mi][nj], a[mi][0], a[mi][1], a[mi][2], a[mi][3],
                             b[nj][0], b[nj][1]);
        }
        __syncthreads();
    }
#undef ISSUE_TILE

    int g = lane >> 2, t4 = lane & 3;
#pragma unroll
    for (int mi = 0; mi < 4; mi++) {
#pragma unroll
        for (int h2 = 0; h2 < 2; h2++) {
            int rloc = wm + mi * 16 + g + h2 * 8;
            if (MODE == 2 || MODE == 3) {
                int rc = m00 + rloc;
                if (rc >= cnt) continue;
                int slot = off + rc;
                if (MODE == 2) {
                    size_t base = (size_t)slot * DFF;
#pragma unroll
                    for (int nj = 0; nj < 4; nj++) {
                        int col = col0 + wn + nj * 8 + 2 * t4;
                        float v0 = gelu_exact(acc[mi][nj][h2 * 2 + 0] + bias[(size_t)e * DFF + col]);
                        float v1 = gelu_exact(acc[mi][nj][h2 * 2 + 1] + bias[(size_t)e * DFF + col + 1]);
                        *(uint32_t*)&g_hbuf[base + col] = packbf(v0, v1);
                    }
                } else {
                    int tok = g_slot_tok[slot];
                    float gt = g_slot_gate[slot];
#pragma unroll
                    for (int nj = 0; nj < 4; nj++) {
                        int col = col0 + wn + nj * 8 + 2 * t4;
                        float v0 = (acc[mi][nj][h2 * 2 + 0] + bias[(size_t)e * DM + col]) * gt;
                        float v1 = (acc[mi][nj][h2 * 2 + 1] + bias[(size_t)e * DM + col + 1]) * gt;
                        atomicAdd(&C[(size_t)tok * DM + col], v0);
                        atomicAdd(&C[(size_t)tok * DM + col + 1], v1);
                    }
                }
            } else if (MODE == 1) {
                int row = m00 + rloc;
#pragma unroll
                for (int nj = 0; nj < 4; nj++) {
                    int col = col0 + wn + nj * 8 + 2 * t4;
                    float v0 = acc[mi][nj][h2 * 2 + 0] + bias[col] + res[(size_t)row * N + col];
                    float v1 = acc[mi][nj][h2 * 2 + 1] + bias[col + 1] + res[(size_t)row * N + col + 1];
                    *(float2*)&C[(size_t)row * N + col] = make_float2(v0, v1);
                }
            } else {  // MODE 4: bf16 out
                int row = m00 + rloc;
#pragma unroll
                for (int nj = 0; nj < 4; nj++) {
                    int col = col0 + wn + nj * 8 + 2 * t4;
                    *(uint32_t*)&outp16[(size_t)row * DM + col] =
                        packbf(acc[mi][nj][h2 * 2 + 0], acc[mi][nj][h2 * 2 + 1]);
                }
            }
        }
    }
}

// ---------------- fused flash attention (bf16 in/out, cp.async, f16x2 exp) ------
__global__ __launch_bounds__(128)
void flash_attn_kernel() {
    int bh = blockIdx.y; int b = bh / NH, h = bh % NH;
    int qt = (int)(gridDim.x - 1) - (int)blockIdx.x;  // heavy tiles first
    int q0 = qt * 64;
    int tid = threadIdx.x, lane = tid & 31, warp = tid >> 5;
    int wq = warp * 16;

    __shared__ unsigned short Qs[64][72];
    __shared__ unsigned short Ks[2][64][72];
    __shared__ unsigned short Vs[2][64][72];

    int lr = tid >> 1, lc = (tid & 1) * 32;

#define FA_ISSUE(BUF, K0)                                                          \
    do {                                                                           \
        const unsigned short* kp = g_kb + (size_t)(b * SEQ + (K0) + lr) * DM + h * HD + lc; \
        const unsigned short* vp = g_vb + (size_t)(b * SEQ + (K0) + lr) * DM + h * HD + lc; \
        uint32_t ka = smem_u32(&Ks[BUF][lr][lc]);                                  \
        uint32_t va = smem_u32(&Vs[BUF][lr][lc]);                                  \
        cp16(ka, kp); cp16(ka + 16, kp + 8); cp16(ka + 32, kp + 16); cp16(ka + 48, kp + 24); \
        cp16(va, vp); cp16(va + 16, vp + 8); cp16(va + 32, vp + 16); cp16(va + 48, vp + 24); \
    } while (0)

    FA_ISSUE(0, 0);
    CP_COMMIT();

    {
        const unsigned short* qp = g_qb + (size_t)(b * SEQ + q0 + lr) * DM + h * HD + lc;
        *(uint4*)&Qs[lr][lc]      = *(const uint4*)(qp);
        *(uint4*)&Qs[lr][lc + 8]  = *(const uint4*)(qp + 8);
        *(uint4*)&Qs[lr][lc + 16] = *(const uint4*)(qp + 16);
        *(uint4*)&Qs[lr][lc + 24] = *(const uint4*)(qp + 24);
    }
    __syncthreads();

    uint32_t qa[4][4];
#pragma unroll
    for (int kc = 0; kc < 4; kc++) {
        uint32_t addr = smem_u32(&Qs[wq + (lane & 15)][kc * 16 + (lane >> 4) * 8]);
        ldsm_x4(qa[kc][0], qa[kc][1], qa[kc][2], qa[kc][3], addr);
    }

    float m_run[2] = {-1e30f, -1e30f};
    float l_run[2] = {0.f, 0.f};
    float oacc[8][4] = {};

    for (int kt = 0; kt <= qt; kt++) {
        int k0 = kt * 64;
        int buf = kt & 1;
        CP_WAIT(0);
        __syncthreads();
        if (kt < qt) { FA_ISSUE(buf ^ 1, k0 + 64); CP_COMMIT(); }

        // S = Q K^T
        float sacc[8][4] = {};
#pragma unroll
        for (int kc = 0; kc < 4; kc++) {
#pragma unroll
            for (int nb = 0; nb < 4; nb++) {
                uint32_t r0, r1, r2, r3;
                uint32_t addr = smem_u32(&Ks[buf][nb * 16 + (lane & 7) + ((lane >> 3) & 1) * 8]
                                            [kc * 16 + (lane >> 4) * 8]);
                ldsm_x4(r0, r1, r2, r3, addr);
                mma_bf16(sacc[nb * 2],     qa[kc][0], qa[kc][1], qa[kc][2], qa[kc][3], r0, r2);
                mma_bf16(sacc[nb * 2 + 1], qa[kc][0], qa[kc][1], qa[kc][2], qa[kc][3], r1, r3);
            }
        }

        // online softmax: exp via ex2.approx.f16x2 (2 exps per MUFU op)
        bool diag = (kt == qt);
#pragma unroll
        for (int half = 0; half < 2; half++) {
            int qrow = q0 + wq + (lane >> 2) + half * 8;
            float vals[16];
#pragma unroll
            for (int nj = 0; nj < 8; nj++) {
                int colg = k0 + nj * 8 + 2 * (lane & 3);
                float v0 = sacc[nj][half * 2 + 0] * 0.125f;
                float v1 = sacc[nj][half * 2 + 1] * 0.125f;
                if (diag) {
                    if (colg > qrow) v0 = -1e30f;
                    if (colg + 1 > qrow) v1 = -1e30f;
                }
                vals[nj * 2] = v0;
                vals[nj * 2 + 1] = v1;
            }
            float tmx = vals[0];
#pragma unroll
            for (int i = 1; i < 16; i++) tmx = fmaxf(tmx, vals[i]);
            tmx = fmaxf(tmx, __shfl_xor_sync(0xffffffffu, tmx, 1));
            tmx = fmaxf(tmx, __shfl_xor_sync(0xffffffffu, tmx, 2));
            float mnew = fmaxf(m_run[half], tmx);
            float corr = __expf(m_run[half] - mnew);
            float rsum = 0.f;
#pragma unroll
            for (int i = 0; i < 8; i++) {
                float t0 = (vals[2 * i + 0] - mnew) * 1.44269504f;
                float t1 = (vals[2 * i + 1] - mnew) * 1.44269504f;
                __half2 ht = __floats2half2_rn(t0, t1);
                uint32_t pb = ex2_f16x2(*(uint32_t*)&ht);
                float2 p = __half22float2(*(__half2*)&pb);
                vals[2 * i + 0] = p.x;
                vals[2 * i + 1] = p.y;
                rsum += p.x + p.y;
            }
            rsum += __shfl_xor_sync(0xffffffffu, rsum, 1);
            rsum += __shfl_xor_sync(0xffffffffu, rsum, 2);
            l_run[half] = l_run[half] * corr + rsum;
            m_run[half] = mnew;
#pragma unroll
            for (int nj = 0; nj < 8; nj++) {
                oacc[nj][half * 2 + 0] *= corr;
                oacc[nj][half * 2 + 1] *= corr;
                sacc[nj][half * 2 + 0] = vals[nj * 2];
                sacc[nj][half * 2 + 1] = vals[nj * 2 + 1];
            }
        }

        // O += P @ V
#pragma unroll
        for (int j = 0; j < 4; j++) {
            uint32_t pa0 = packbf(sacc[2 * j][0], sacc[2 * j][1]);
            uint32_t pa1 = packbf(sacc[2 * j][2], sacc[2 * j][3]);
            uint32_t pa2 = packbf(sacc[2 * j + 1][0], sacc[2 * j + 1][1]);
            uint32_t pa3 = packbf(sacc[2 * j + 1][2], sacc[2 * j + 1][3]);
#pragma unroll
            for (int nb = 0; nb < 2; nb++) {
                uint32_t b0, b1, b2, b3;
                uint32_t addr = smem_u32(&Vs[buf][j * 16 + (lane & 15)][nb * 32 + (lane >> 4) * 8]);
                ldsm_x4_t(b0, b1, b2, b3, addr);
                mma_bf16(oacc[nb * 4 + 0], pa0, pa1, pa2, pa3, b0, b1);
                mma_bf16(oacc[nb * 4 + 1], pa0, pa1, pa2, pa3, b2, b3);
                addr = smem_u32(&Vs[buf][j * 16 + (lane & 15)][nb * 32 + 16 + (lane >> 4) * 8]);
                ldsm_x4_t(b0, b1, b2, b3, addr);
                mma_bf16(oacc[nb * 4 + 2], pa0, pa1, pa2, pa3, b0, b1);
                mma_bf16(oacc[nb * 4 + 3], pa0, pa1, pa2, pa3, b2, b3);
            }
        }
    }
#undef FA_ISSUE

    // write O (bf16)
#pragma unroll
    for (int half = 0; half < 2; half++) {
        float inv = 1.0f / l_run[half];
        int row = q0 + wq + (lane >> 2) + half * 8;
        unsigned short* dst = g_attnb + (size_t)(b * SEQ + row) * DM + h * HD;
#pragma unroll
        for (int nj = 0; nj < 8; nj++) {
            int col = nj * 8 + 2 * (lane & 3);
            *(uint32_t*)&dst[col] = packbf(oacc[nj][half * 2 + 0] * inv,
                                           oacc[nj][half * 2 + 1] * inv);
        }
    }
}

// ---------------- layernorm: writes bf16 always, fp32 optionally ----------------
__global__ void ln_kernel(const float* __restrict__ x, const float* __restrict__ gam,
                          const float* __restrict__ bet, float* __restrict__ yf,
                          unsigned short* __restrict__ yb) {
    int row = blockIdx.x;
    int tid = threadIdx.x;  // 256
    __shared__ float sx[DM];
    __shared__ float red[256];
    const float* xr = x + (size_t)row * DM;
    float s = 0.f;
    for (int i = tid; i < DM; i += 256) { float v = xr[i]; sx[i] = v; s += v; }
    red[tid] = s; __syncthreads();
    for (int o = 128; o > 0; o >>= 1) { if (tid < o) red[tid] += red[tid + o]; __syncthreads(); }
    float m = red[0] * (1.0f / DM);
    __syncthreads();
    float s2 = 0.f;
    for (int i = tid; i < DM; i += 256) { float d = sx[i] - m; s2 += d * d; }
    red[tid] = s2; __syncthreads();
    for (int o = 128; o > 0; o >>= 1) { if (tid < o) red[tid] += red[tid + o]; __syncthreads(); }
    float var = red[0] * (1.0f / DM);
    float r = rsqrtf(var + 1e-5f);
    for (int i = tid; i < DM; i += 256) {
        float v = (sx[i] - m) * r * gam[i] + bet[i];
        if (yf) yf[(size_t)row * DM + i] = v;
        yb[(size_t)row * DM + i] = __bfloat16_as_ushort(__float2bfloat16(v));
    }
}

// ---------------- router ----------------
__global__ void router_kernel(const float* __restrict__ Wr, const float* __restrict__ br) {
    int t = blockIdx.x, tid = threadIdx.x;  // 64 threads
    float acc[NEXP] = {};
    const float* xr = g_xn2 + (size_t)t * DM;
    for (int d = tid; d < DM; d += 64) {
        float xv = xr[d];
        const float* w = Wr + (size_t)d * NEXP;
#pragma unroll
        for (int e = 0; e < NEXP; e++) acc[e] += xv * w[e];
    }
    __shared__ float sh[64][NEXP + 1];
#pragma unroll
    for (int e = 0; e < NEXP; e++) sh[tid][e] = acc[e];
    __syncthreads();
    if (tid < NEXP) {
        float s = br[tid];
        for (int i = 0; i < 64; i++) s += sh[i][tid];
        sh[0][tid] = s;
    }
    __syncthreads();
    if (tid == 0) {
        float l[NEXP];
#pragma unroll
        for (int e = 0; e < NEXP; e++) l[e] = sh[0][e];
        int i1 = 0;
        for (int e = 1; e < NEXP; e++) if (l[e] > l[i1]) i1 = e;
        int i2 = (i1 == 0) ? 1 : 0;
        for (int e = 0; e < NEXP; e++) if (e != i1 && l[e] > l[i2]) i2 = e;
        float g1 = 1.0f / (1.0f + expf(l[i2] - l[i1]));
        float g2 = 1.0f - g1;
        g_top_e[2 * t] = i1; g_top_g[2 * t] = g1;
        g_top_e[2 * t + 1] = i2; g_top_g[2 * t + 1] = g2;
        atomicAdd(&g_cnt[i1], 1);
        atomicAdd(&g_cnt[i2], 1);
    }
}

__global__ void offsets_kernel() {
    if (threadIdx.x == 0) {
        int acc = 0;
#pragma unroll
        for (int e = 0; e < NEXP; e++) { g_off[e] = acc; acc += g_cnt[e]; }
    }
}

__global__ void scatter_kernel() {
    int i = blockIdx.x * 256 + threadIdx.x;
    if (i >= NSLOTS) return;
    int e = g_top_e[i];
    int p = atomicAdd(&g_fill[e], 1);
    int slot = g_off[e] + p;
    g_slot_tok[slot] = i >> 1;
    g_slot_gate[slot] = g_top_g[i];
}

// ---------------- launch ----------------
extern "C" void kernel_launch(void* const* d_in, const int* in_sizes, int n_in,
                              void* d_out, int out_size) {
    const float* x     = (const float*)d_in[0];
    const float* ln1_g = (const float*)d_in[1];
    const float* ln1_b = (const float*)d_in[2];
    const float* Wq    = (const float*)d_in[3];
    const float* Wk    = (const float*)d_in[4];
    const float* Wv    = (const float*)d_in[5];
    const float* Wo    = (const float*)d_in[6];
    const float* bo    = (const float*)d_in[7];
    const float* ln2_g = (const float*)d_in[8];
    const float* ln2_b = (const float*)d_in[9];
    const float* Wr    = (const float*)d_in[10];
    const float* br    = (const float*)d_in[11];
    const float* W1    = (const float*)d_in[12];
    const float* b1    = (const float*)d_in[13];
    const float* W2    = (const float*)d_in[14];
    const float* b2    = (const float*)d_in[15];
    float* out = (float*)d_out;

    float* xn2_p;
    unsigned short *xn1b_p, *xn2b_p, *w1b_p, *w2b_p;
    cudaGetSymbolAddress((void**)&xn2_p, g_xn2);
    cudaGetSymbolAddress((void**)&xn1b_p, g_xn1b);
    cudaGetSymbolAddress((void**)&xn2b_p, g_xn2b);
    cudaGetSymbolAddress((void**)&w1b_p, g_w1b);
    cudaGetSymbolAddress((void**)&w2b_p, g_w2b);

    const int BG_SMEM = (4 * 5120 + 4 * 4352) * 2;  // 75776 B (4-stage)
    cudaFuncSetAttribute(bgemm<1>, cudaFuncAttributeMaxDynamicSharedMemorySize, BG_SMEM);
    cudaFuncSetAttribute(bgemm<2>, cudaFuncAttributeMaxDynamicSharedMemorySize, BG_SMEM);
    cudaFuncSetAttribute(bgemm<3>, cudaFuncAttributeMaxDynamicSharedMemorySize, BG_SMEM);
    cudaFuncSetAttribute(bgemm<4>, cudaFuncAttributeMaxDynamicSharedMemorySize, BG_SMEM);

    zero_cnt_kernel<<<1, 32>>>();
    // weight conversions
    cvt_qkvo_kernel<<<dim3(576, 4), 256>>>(Wq, Wk, Wv, Wo);
    cvt_big_kernel<<<9216, 256>>>(W1, w1b_p);
    cvt_big_kernel<<<9216, 256>>>(W2, w2b_p);

    ln_kernel<<<TOKENS, 256>>>(x, ln1_g, ln1_b, nullptr, xn1b_p);

    // fused QKV (bf16 out)
    bgemm<4><<<dim3(18, TOKENS / 128), 256, BG_SMEM>>>(nullptr, nullptr, nullptr, DM, DM);

    flash_attn_kernel<<<dim3(SEQ / 64, BH), 128>>>();

    // h = x + attn @ Wo + bo -> d_out (fp32)
    bgemm<1><<<dim3(DM / 128, TOKENS / 128), 256, BG_SMEM>>>(bo, x, out, DM, DM);

    ln_kernel<<<TOKENS, 256>>>(out, ln2_g, ln2_b, xn2_p, xn2b_p);

    router_kernel<<<TOKENS, 64>>>(Wr, br);
    offsets_kernel<<<1, 32>>>();
    scatter_kernel<<<(NSLOTS + 255) / 256, 256>>>();

    bgemm<2><<<dim3(DFF / 128, TOKENS / 128, NEXP), 256, BG_SMEM>>>(b1, nullptr, nullptr, DFF, DM);
    bgemm<3><<<dim3(DM / 128, TOKENS / 128, NEXP), 256, BG_SMEM>>>(b2, nullptr, out, DM, DFF);
}